// round 4
// baseline (speedup 1.0000x reference)
#include <cuda_runtime.h>
#include <math.h>
#include <stdint.h>

#define S_LEN 2048
#define DIM 2048
#define NH 32
#define NKV 8
#define HD 64
#define QK_SCALE 0.125f   // 1/sqrt(64)

// ---- scratch (device globals; no allocation allowed) ----
__device__ float g_q[S_LEN * NH * HD];
__device__ float g_k[S_LEN * NKV * HD];
__device__ float g_v[S_LEN * NKV * HD];
__device__ float g_o[S_LEN * NH * HD];

__device__ __forceinline__ uint32_t f2tf32(float f) {
    uint32_t t;
    asm("cvt.rna.tf32.f32 %0, %1;" : "=r"(t) : "f"(f));
    return t;
}

__device__ __forceinline__ void mma_tf32(float* c, const uint32_t* a, const uint32_t* b) {
    asm volatile(
        "mma.sync.aligned.m16n8k8.row.col.f32.tf32.tf32.f32 "
        "{%0,%1,%2,%3}, {%4,%5,%6,%7}, {%8,%9}, {%0,%1,%2,%3};"
        : "+f"(c[0]), "+f"(c[1]), "+f"(c[2]), "+f"(c[3])
        : "r"(a[0]), "r"(a[1]), "r"(a[2]), "r"(a[3]), "r"(b[0]), "r"(b[1]));
}

// Permuted-k smem layout: within each 8-wide k group, element k is stored at
// offset (k&3)*2 + (k>>2).  Fragment pairs (lk, lk+4) are then adjacent words
// -> one LDS.64 per pair.

// ============================================================================
// TF32 GEMM NT core: C[m,n] = sum_k A[m,k]*B[n,k] + bias[n]
// Block 128x128x16, 8 warps, warp tile 32x64. Double-buffered smem,
// one __syncthreads per K-slab. Permuted-k layout -> LDS.64 fragments.
// ============================================================================
#define SMS 20

__device__ __forceinline__ void gemm_core(
    const float* __restrict__ A, const float* __restrict__ B,
    const float* __restrict__ bias, float* __restrict__ C,
    int N, int K, int m0, int n0)
{
    __shared__ __align__(16) uint32_t As[2][128 * SMS];
    __shared__ __align__(16) uint32_t Bs[2][128 * SMS];

    const int tid = threadIdx.x;
    const int wid = tid >> 5;
    const int wm = wid & 3;
    const int wn = wid >> 2;
    const int l = tid & 31;
    const int l4 = l >> 2;
    const int lk2 = (l & 3) * 2;

    const int grow = tid >> 2;
    const int gk = (tid & 3) * 4;
    // permuted store base for 4 consecutive k starting at gk:
    const int pbase = ((gk >> 3) * 8) + ((gk & 4) >> 2);

    float acc[2][8][4];
    #pragma unroll
    for (int i = 0; i < 2; i++)
        #pragma unroll
        for (int j = 0; j < 8; j++)
            #pragma unroll
            for (int q = 0; q < 4; q++) acc[i][j][q] = 0.f;

    const float* Ab = A + (size_t)(m0 + grow) * K + gk;
    const float* Bb = B + (size_t)(n0 + grow) * K + gk;

    float4 pa0 = *(const float4*)(Ab);
    float4 pa1 = *(const float4*)(Ab + (size_t)64 * K);
    float4 pb0 = *(const float4*)(Bb);
    float4 pb1 = *(const float4*)(Bb + (size_t)64 * K);

    // store stage 0 (permuted: offsets +0,+2,+4,+6)
    {
        uint32_t* pA = As[0] + grow * SMS + pbase;
        pA[0] = f2tf32(pa0.x); pA[2] = f2tf32(pa0.y); pA[4] = f2tf32(pa0.z); pA[6] = f2tf32(pa0.w);
        uint32_t* pA2 = pA + 64 * SMS;
        pA2[0] = f2tf32(pa1.x); pA2[2] = f2tf32(pa1.y); pA2[4] = f2tf32(pa1.z); pA2[6] = f2tf32(pa1.w);
        uint32_t* pB = Bs[0] + grow * SMS + pbase;
        pB[0] = f2tf32(pb0.x); pB[2] = f2tf32(pb0.y); pB[4] = f2tf32(pb0.z); pB[6] = f2tf32(pb0.w);
        uint32_t* pB2 = pB + 64 * SMS;
        pB2[0] = f2tf32(pb1.x); pB2[2] = f2tf32(pb1.y); pB2[4] = f2tf32(pb1.z); pB2[6] = f2tf32(pb1.w);
    }

    int cur = 0;
    for (int kt = 0; kt < K; kt += 16) {
        __syncthreads();
        const bool more = (kt + 16) < K;
        if (more) {
            pa0 = *(const float4*)(Ab + kt + 16);
            pa1 = *(const float4*)(Ab + (size_t)64 * K + kt + 16);
            pb0 = *(const float4*)(Bb + kt + 16);
            pb1 = *(const float4*)(Bb + (size_t)64 * K + kt + 16);
        }

        const uint32_t* Ac = As[cur];
        const uint32_t* Bc = Bs[cur];
        #pragma unroll
        for (int k0 = 0; k0 < 16; k0 += 8) {
            uint32_t a[2][4], b[8][2];
            #pragma unroll
            for (int tm = 0; tm < 2; tm++) {
                const uint32_t* base = Ac + (wm * 32 + tm * 16 + l4) * SMS + k0 + lk2;
                const uint2 t0 = *(const uint2*)(base);
                const uint2 t1 = *(const uint2*)(base + 8 * SMS);
                a[tm][0] = t0.x; a[tm][2] = t0.y;
                a[tm][1] = t1.x; a[tm][3] = t1.y;
            }
            #pragma unroll
            for (int tn = 0; tn < 8; tn++) {
                const uint2 t = *(const uint2*)(Bc + (wn * 64 + tn * 8 + l4) * SMS + k0 + lk2);
                b[tn][0] = t.x; b[tn][1] = t.y;
            }
            #pragma unroll
            for (int tm = 0; tm < 2; tm++)
                #pragma unroll
                for (int tn = 0; tn < 8; tn++)
                    mma_tf32(acc[tm][tn], a[tm], b[tn]);
        }

        if (more) {
            const int nxt = cur ^ 1;
            uint32_t* pA = As[nxt] + grow * SMS + pbase;
            pA[0] = f2tf32(pa0.x); pA[2] = f2tf32(pa0.y); pA[4] = f2tf32(pa0.z); pA[6] = f2tf32(pa0.w);
            uint32_t* pA2 = pA + 64 * SMS;
            pA2[0] = f2tf32(pa1.x); pA2[2] = f2tf32(pa1.y); pA2[4] = f2tf32(pa1.z); pA2[6] = f2tf32(pa1.w);
            uint32_t* pB = Bs[nxt] + grow * SMS + pbase;
            pB[0] = f2tf32(pb0.x); pB[2] = f2tf32(pb0.y); pB[4] = f2tf32(pb0.z); pB[6] = f2tf32(pb0.w);
            uint32_t* pB2 = pB + 64 * SMS;
            pB2[0] = f2tf32(pb1.x); pB2[2] = f2tf32(pb1.y); pB2[4] = f2tf32(pb1.z); pB2[6] = f2tf32(pb1.w);
        }
        cur ^= 1;
    }

    #pragma unroll
    for (int tm = 0; tm < 2; tm++) {
        const int row0 = m0 + wm * 32 + tm * 16 + l4;
        #pragma unroll
        for (int tn = 0; tn < 8; tn++) {
            const int col = n0 + wn * 64 + tn * 8 + lk2;
            const float b0 = bias[col];
            const float b1 = bias[col + 1];
            float2 v0 = make_float2(acc[tm][tn][0] + b0, acc[tm][tn][1] + b1);
            float2 v1 = make_float2(acc[tm][tn][2] + b0, acc[tm][tn][3] + b1);
            *(float2*)(C + (size_t)row0 * N + col) = v0;
            *(float2*)(C + (size_t)(row0 + 8) * N + col) = v1;
        }
    }
}

__global__ void __launch_bounds__(256, 2) gemm_tf32_single(
    const float* __restrict__ A, const float* __restrict__ B,
    const float* __restrict__ bias, float* __restrict__ C, int N, int K)
{
    gemm_core(A, B, bias, C, N, K, blockIdx.y * 128, blockIdx.x * 128);
}

__global__ void __launch_bounds__(256, 2) gemm_tf32_kv(
    const float* __restrict__ A,
    const float* __restrict__ Bk, const float* __restrict__ bk, float* __restrict__ Ck,
    const float* __restrict__ Bv, const float* __restrict__ bv, float* __restrict__ Cv,
    int N, int K)
{
    const float* B = blockIdx.z ? Bv : Bk;
    const float* bias = blockIdx.z ? bv : bk;
    float* C = blockIdx.z ? Cv : Ck;
    gemm_core(A, B, bias, C, N, K, blockIdx.y * 128, blockIdx.x * 128);
}

// ============================================================================
// RoPE in-place on g_q and g_k.
// ============================================================================
__global__ void rope_kernel(const float* __restrict__ rc)
{
    const int idx = blockIdx.x * blockDim.x + threadIdx.x;
    const int totalq = S_LEN * NH * 32;
    const int totalk = S_LEN * NKV * 32;
    if (idx < totalq) {
        const int d = idx & 31;
        const int sh = idx >> 5;
        const int h = sh & (NH - 1);
        const int s = sh >> 5;
        const float c = rc[s * HD + d];
        const float sn = rc[s * HD + 32 + d];
        float* p = g_q + ((size_t)s * NH + h) * HD;
        const float x1 = p[d], x2 = p[d + 32];
        p[d] = x1 * c - x2 * sn;
        p[d + 32] = x1 * sn + x2 * c;
    } else if (idx < totalq + totalk) {
        const int e = idx - totalq;
        const int d = e & 31;
        const int sh = e >> 5;
        const int h = sh & (NKV - 1);
        const int s = sh >> 3;
        const float c = rc[s * HD + d];
        const float sn = rc[s * HD + 32 + d];
        float* p = g_k + ((size_t)s * NKV + h) * HD;
        const float x1 = p[d], x2 = p[d + 32];
        p[d] = x1 * c - x2 * sn;
        p[d + 32] = x1 * sn + x2 * c;
    }
}

// ============================================================================
// Flash attention, TF32 tensor cores, P kept in registers.
// The P.V mma's k-axis is permuted by sigma(p)=2p (p<4), 2(p-4)+1 (p>=4),
// applied to BOTH operands: the S-tile C-fragment then doubles as the P
// A-fragment ({c0,c2,c1,c3}); V in natural key order pairs as LDS.64.
// K smem uses the permuted-k layout (LDS.64 b-fragments). Q staged via Ks.
// ============================================================================
#define FSTR 68

__global__ void __launch_bounds__(128, 4) flash_tc(const float* __restrict__ sinks)
{
    __shared__ __align__(16) uint32_t Ks[64 * FSTR];
    __shared__ __align__(16) uint32_t Vs[64 * FSTR];

    const int h = blockIdx.y;
    const int kvh = h >> 2;
    const int qt = (int)gridDim.x - 1 - (int)blockIdx.x;   // heaviest first
    const int q0 = qt * 64;
    const int tid = threadIdx.x;
    const int w = tid >> 5;
    const int l = tid & 31;
    const int l4 = l >> 2;
    const int lk2 = (l & 3) * 2;

    // ---- stage Q tile (scaled, tf32, permuted-k) through Ks ----
    #pragma unroll
    for (int it = 0; it < 8; it++) {
        const int e = tid + it * 128;
        const int row = e >> 4, c4 = e & 15;
        float4 t = *(const float4*)(g_q + (size_t)(q0 + row) * (NH * HD) + h * HD + c4 * 4);
        uint32_t* p = Ks + row * FSTR + (c4 >> 1) * 8 + (c4 & 1);
        p[0] = f2tf32(t.x * QK_SCALE);
        p[2] = f2tf32(t.y * QK_SCALE);
        p[4] = f2tf32(t.z * QK_SCALE);
        p[6] = f2tf32(t.w * QK_SCALE);
    }
    __syncthreads();

    uint32_t qf[8][4];
    #pragma unroll
    for (int kc = 0; kc < 8; kc++) {
        const uint32_t* base = Ks + (w * 16 + l4) * FSTR + kc * 8 + lk2;
        const uint2 t0 = *(const uint2*)(base);
        const uint2 t1 = *(const uint2*)(base + 8 * FSTR);
        qf[kc][0] = t0.x; qf[kc][2] = t0.y;
        qf[kc][1] = t1.x; qf[kc][3] = t1.y;
    }

    float o[8][4];
    #pragma unroll
    for (int i = 0; i < 8; i++)
        #pragma unroll
        for (int j = 0; j < 4; j++) o[i][j] = 0.f;
    float m0 = -1e30f, m1 = -1e30f, l0 = 0.f, l1 = 0.f;

    for (int jt = 0; jt <= qt; jt++) {
        const int j0 = jt * 64;
        __syncthreads();   // qf loads / prev PV reads done before overwrite
        // ---- load K (permuted-k) and V (transposed, natural key order) ----
        #pragma unroll
        for (int it = 0; it < 8; it++) {
            const int e = tid + it * 128;
            const int row = e >> 4, c4 = e & 15;
            const size_t base = (size_t)(j0 + row) * (NKV * HD) + kvh * HD + c4 * 4;
            float4 kv = *(const float4*)(g_k + base);
            uint32_t* kp = Ks + row * FSTR + (c4 >> 1) * 8 + (c4 & 1);
            kp[0] = f2tf32(kv.x); kp[2] = f2tf32(kv.y);
            kp[4] = f2tf32(kv.z); kp[6] = f2tf32(kv.w);
            float4 vv = *(const float4*)(g_v + base);
            Vs[(c4 * 4 + 0) * FSTR + row] = f2tf32(vv.x);
            Vs[(c4 * 4 + 1) * FSTR + row] = f2tf32(vv.y);
            Vs[(c4 * 4 + 2) * FSTR + row] = f2tf32(vv.z);
            Vs[(c4 * 4 + 3) * FSTR + row] = f2tf32(vv.w);
        }
        __syncthreads();

        // ---- S = Q K^T (16 rows x 64 keys per warp) ----
        float c[8][4];
        #pragma unroll
        for (int i = 0; i < 8; i++)
            #pragma unroll
            for (int j = 0; j < 4; j++) c[i][j] = 0.f;
        #pragma unroll
        for (int kc = 0; kc < 8; kc++) {
            #pragma unroll
            for (int nt = 0; nt < 8; nt++) {
                uint32_t b[2];
                const uint2 t = *(const uint2*)(Ks + (nt * 8 + l4) * FSTR + kc * 8 + lk2);
                b[0] = t.x; b[1] = t.y;
                mma_tf32(c[nt], qf[kc], b);
            }
        }

        // ---- causal mask (diagonal tile only) ----
        if (jt == qt) {
            const int row0 = w * 16 + l4, row1 = row0 + 8;
            #pragma unroll
            for (int nt = 0; nt < 8; nt++) {
                const int col = nt * 8 + lk2;
                if (col > row0)     c[nt][0] = -1e30f;
                if (col + 1 > row0) c[nt][1] = -1e30f;
                if (col > row1)     c[nt][2] = -1e30f;
                if (col + 1 > row1) c[nt][3] = -1e30f;
            }
        }

        // ---- online softmax (rows l4 and l4+8 of warp tile) ----
        float rmax0 = -1e30f, rmax1 = -1e30f;
        #pragma unroll
        for (int nt = 0; nt < 8; nt++) {
            rmax0 = fmaxf(rmax0, fmaxf(c[nt][0], c[nt][1]));
            rmax1 = fmaxf(rmax1, fmaxf(c[nt][2], c[nt][3]));
        }
        rmax0 = fmaxf(rmax0, __shfl_xor_sync(0xffffffffu, rmax0, 1));
        rmax0 = fmaxf(rmax0, __shfl_xor_sync(0xffffffffu, rmax0, 2));
        rmax1 = fmaxf(rmax1, __shfl_xor_sync(0xffffffffu, rmax1, 1));
        rmax1 = fmaxf(rmax1, __shfl_xor_sync(0xffffffffu, rmax1, 2));

        const float mn0 = fmaxf(m0, rmax0);
        const float mn1 = fmaxf(m1, rmax1);
        const float al0 = __expf(m0 - mn0);
        const float al1 = __expf(m1 - mn1);
        m0 = mn0; m1 = mn1;

        float rs0 = 0.f, rs1 = 0.f;
        #pragma unroll
        for (int nt = 0; nt < 8; nt++) {
            c[nt][0] = __expf(c[nt][0] - mn0); rs0 += c[nt][0];
            c[nt][1] = __expf(c[nt][1] - mn0); rs0 += c[nt][1];
            c[nt][2] = __expf(c[nt][2] - mn1); rs1 += c[nt][2];
            c[nt][3] = __expf(c[nt][3] - mn1); rs1 += c[nt][3];
        }
        rs0 += __shfl_xor_sync(0xffffffffu, rs0, 1);
        rs0 += __shfl_xor_sync(0xffffffffu, rs0, 2);
        rs1 += __shfl_xor_sync(0xffffffffu, rs1, 1);
        rs1 += __shfl_xor_sync(0xffffffffu, rs1, 2);
        l0 = l0 * al0 + rs0;
        l1 = l1 * al1 + rs1;

        #pragma unroll
        for (int nt = 0; nt < 8; nt++) {
            o[nt][0] *= al0; o[nt][1] *= al0;
            o[nt][2] *= al1; o[nt][3] *= al1;
        }

        // ---- O += P V : P A-fragment comes straight from c registers ----
        #pragma unroll
        for (int kc = 0; kc < 8; kc++) {
            uint32_t a[4];
            a[0] = f2tf32(c[kc][0]);   // (row l4,   key 2lk)   -> k=lk
            a[1] = f2tf32(c[kc][2]);   // (row l4+8, key 2lk)   -> k=lk
            a[2] = f2tf32(c[kc][1]);   // (row l4,   key 2lk+1) -> k=lk+4
            a[3] = f2tf32(c[kc][3]);   // (row l4+8, key 2lk+1) -> k=lk+4
            #pragma unroll
            for (int nt = 0; nt < 8; nt++) {
                uint32_t b[2];
                const uint2 t = *(const uint2*)(Vs + (nt * 8 + l4) * FSTR + kc * 8 + lk2);
                b[0] = t.x; b[1] = t.y;
                mma_tf32(o[nt], a, b);
            }
        }
    }

    // ---- epilogue: lse, sink sigmoid, normalize, store ----
    const float sk = sinks[h];
    const float lse0 = m0 + __logf(l0);
    const float lse1 = m1 + __logf(l1);
    const float w0 = (1.f / (1.f + __expf(sk - lse0))) / l0;
    const float w1 = (1.f / (1.f + __expf(sk - lse1))) / l1;
    const int row0 = q0 + w * 16 + l4;
    #pragma unroll
    for (int nt = 0; nt < 8; nt++) {
        const int col = h * HD + nt * 8 + lk2;
        float2 v0 = make_float2(o[nt][0] * w0, o[nt][1] * w0);
        float2 v1 = make_float2(o[nt][2] * w1, o[nt][3] * w1);
        *(float2*)(g_o + (size_t)row0 * (NH * HD) + col) = v0;
        *(float2*)(g_o + (size_t)(row0 + 8) * (NH * HD) + col) = v1;
    }
}

// ============================================================================
// launch
// ============================================================================
extern "C" void kernel_launch(void* const* d_in, const int* in_sizes, int n_in,
                              void* d_out, int out_size)
{
    const float* x     = (const float*)d_in[0];
    const float* rc    = (const float*)d_in[1];
    const float* wq_w  = (const float*)d_in[2];
    const float* wq_b  = (const float*)d_in[3];
    const float* wk_w  = (const float*)d_in[4];
    const float* wk_b  = (const float*)d_in[5];
    const float* wv_w  = (const float*)d_in[6];
    const float* wv_b  = (const float*)d_in[7];
    const float* wo_w  = (const float*)d_in[8];
    const float* wo_b  = (const float*)d_in[9];
    const float* sinks = (const float*)d_in[10];
    float* out = (float*)d_out;

    float *qp, *kp, *vp, *op;
    cudaGetSymbolAddress((void**)&qp, g_q);
    cudaGetSymbolAddress((void**)&kp, g_k);
    cudaGetSymbolAddress((void**)&vp, g_v);
    cudaGetSymbolAddress((void**)&op, g_o);

    // Q projection
    gemm_tf32_single<<<dim3((NH * HD) / 128, S_LEN / 128), 256>>>(x, wq_w, wq_b, qp, NH * HD, DIM);
    // fused K+V projections
    gemm_tf32_kv<<<dim3((NKV * HD) / 128, S_LEN / 128, 2), 256>>>(
        x, wk_w, wk_b, kp, wv_w, wv_b, vp, NKV * HD, DIM);

    // RoPE
    {
        const int total = S_LEN * NH * 32 + S_LEN * NKV * 32;
        rope_kernel<<<(total + 255) / 256, 256>>>(rc);
    }

    // flash attention (tf32 tensor cores, P in registers)
    flash_tc<<<dim3(S_LEN / 64, NH), 128>>>(sinks);

    // output projection
    gemm_tf32_single<<<dim3(DIM / 128, S_LEN / 128), 256>>>(op, wo_w, wo_b, out, DIM, DIM);
}

// round 5
// speedup vs baseline: 1.2257x; 1.2257x over previous
#include <cuda_runtime.h>
#include <math.h>
#include <stdint.h>

#define S_LEN 2048
#define DIM 2048
#define NH 32
#define NKV 8
#define HD 64
#define QK_SCALE 0.125f   // 1/sqrt(64)

// ---- scratch (device globals; no allocation allowed) ----
__device__ float g_q[S_LEN * NH * HD];
__device__ float g_k[S_LEN * NKV * HD];
__device__ float g_v[S_LEN * NKV * HD];
__device__ float g_o[S_LEN * NH * HD];

__device__ __forceinline__ uint32_t f2tf32(float f) {
    uint32_t t;
    asm("cvt.rna.tf32.f32 %0, %1;" : "=r"(t) : "f"(f));
    return t;
}

__device__ __forceinline__ void mma_tf32(float* c, const uint32_t* a, const uint32_t* b) {
    asm volatile(
        "mma.sync.aligned.m16n8k8.row.col.f32.tf32.tf32.f32 "
        "{%0,%1,%2,%3}, {%4,%5,%6,%7}, {%8,%9}, {%0,%1,%2,%3};"
        : "+f"(c[0]), "+f"(c[1]), "+f"(c[2]), "+f"(c[3])
        : "r"(a[0]), "r"(a[1]), "r"(a[2]), "r"(a[3]), "r"(b[0]), "r"(b[1]));
}

// ============================================================================
// TF32 GEMM NT core (round-3 layout: 32-bit conflict-free fragment LDS).
// Block 128x128x16, 8 warps, warp tile 32x64, double-buffered smem.
// ============================================================================
#define SMS 20

__device__ __forceinline__ void gemm_core(
    const float* __restrict__ A, const float* __restrict__ B,
    const float* __restrict__ bias, float* __restrict__ C,
    int N, int K, int m0, int n0)
{
    __shared__ uint32_t As[2][128 * SMS];
    __shared__ uint32_t Bs[2][128 * SMS];

    const int tid = threadIdx.x;
    const int wid = tid >> 5;
    const int wm = wid & 3;
    const int wn = wid >> 2;
    const int l = tid & 31;
    const int l4 = l >> 2;
    const int lk = l & 3;

    const int grow = tid >> 2;
    const int gk = (tid & 3) * 4;

    float acc[2][8][4];
    #pragma unroll
    for (int i = 0; i < 2; i++)
        #pragma unroll
        for (int j = 0; j < 8; j++)
            #pragma unroll
            for (int q = 0; q < 4; q++) acc[i][j][q] = 0.f;

    const float* Ab = A + (size_t)(m0 + grow) * K + gk;
    const float* Bb = B + (size_t)(n0 + grow) * K + gk;

    float4 pa0 = *(const float4*)(Ab);
    float4 pa1 = *(const float4*)(Ab + (size_t)64 * K);
    float4 pb0 = *(const float4*)(Bb);
    float4 pb1 = *(const float4*)(Bb + (size_t)64 * K);

    {
        uint32_t* pA = As[0] + grow * SMS + gk;
        pA[0] = f2tf32(pa0.x); pA[1] = f2tf32(pa0.y); pA[2] = f2tf32(pa0.z); pA[3] = f2tf32(pa0.w);
        uint32_t* pA2 = pA + 64 * SMS;
        pA2[0] = f2tf32(pa1.x); pA2[1] = f2tf32(pa1.y); pA2[2] = f2tf32(pa1.z); pA2[3] = f2tf32(pa1.w);
        uint32_t* pB = Bs[0] + grow * SMS + gk;
        pB[0] = f2tf32(pb0.x); pB[1] = f2tf32(pb0.y); pB[2] = f2tf32(pb0.z); pB[3] = f2tf32(pb0.w);
        uint32_t* pB2 = pB + 64 * SMS;
        pB2[0] = f2tf32(pb1.x); pB2[1] = f2tf32(pb1.y); pB2[2] = f2tf32(pb1.z); pB2[3] = f2tf32(pb1.w);
    }

    int cur = 0;
    for (int kt = 0; kt < K; kt += 16) {
        __syncthreads();
        const bool more = (kt + 16) < K;
        if (more) {
            pa0 = *(const float4*)(Ab + kt + 16);
            pa1 = *(const float4*)(Ab + (size_t)64 * K + kt + 16);
            pb0 = *(const float4*)(Bb + kt + 16);
            pb1 = *(const float4*)(Bb + (size_t)64 * K + kt + 16);
        }

        const uint32_t* Ac = As[cur];
        const uint32_t* Bc = Bs[cur];
        #pragma unroll
        for (int k0 = 0; k0 < 16; k0 += 8) {
            uint32_t a[2][4], b[8][2];
            #pragma unroll
            for (int tm = 0; tm < 2; tm++) {
                const uint32_t* base = Ac + (wm * 32 + tm * 16 + l4) * SMS + k0 + lk;
                a[tm][0] = base[0];
                a[tm][1] = base[8 * SMS];
                a[tm][2] = base[4];
                a[tm][3] = base[8 * SMS + 4];
            }
            #pragma unroll
            for (int tn = 0; tn < 8; tn++) {
                const uint32_t* bb = Bc + (wn * 64 + tn * 8 + l4) * SMS + k0 + lk;
                b[tn][0] = bb[0];
                b[tn][1] = bb[4];
            }
            #pragma unroll
            for (int tm = 0; tm < 2; tm++)
                #pragma unroll
                for (int tn = 0; tn < 8; tn++)
                    mma_tf32(acc[tm][tn], a[tm], b[tn]);
        }

        if (more) {
            const int nxt = cur ^ 1;
            uint32_t* pA = As[nxt] + grow * SMS + gk;
            pA[0] = f2tf32(pa0.x); pA[1] = f2tf32(pa0.y); pA[2] = f2tf32(pa0.z); pA[3] = f2tf32(pa0.w);
            uint32_t* pA2 = pA + 64 * SMS;
            pA2[0] = f2tf32(pa1.x); pA2[1] = f2tf32(pa1.y); pA2[2] = f2tf32(pa1.z); pA2[3] = f2tf32(pa1.w);
            uint32_t* pB = Bs[nxt] + grow * SMS + gk;
            pB[0] = f2tf32(pb0.x); pB[1] = f2tf32(pb0.y); pB[2] = f2tf32(pb0.z); pB[3] = f2tf32(pb0.w);
            uint32_t* pB2 = pB + 64 * SMS;
            pB2[0] = f2tf32(pb1.x); pB2[1] = f2tf32(pb1.y); pB2[2] = f2tf32(pb1.z); pB2[3] = f2tf32(pb1.w);
        }
        cur ^= 1;
    }

    #pragma unroll
    for (int tm = 0; tm < 2; tm++) {
        const int row0 = m0 + wm * 32 + tm * 16 + l4;
        #pragma unroll
        for (int tn = 0; tn < 8; tn++) {
            const int col = n0 + wn * 64 + tn * 8 + lk * 2;
            const float b0 = bias[col];
            const float b1 = bias[col + 1];
            float2 v0 = make_float2(acc[tm][tn][0] + b0, acc[tm][tn][1] + b1);
            float2 v1 = make_float2(acc[tm][tn][2] + b0, acc[tm][tn][3] + b1);
            *(float2*)(C + (size_t)row0 * N + col) = v0;
            *(float2*)(C + (size_t)(row0 + 8) * N + col) = v1;
        }
    }
}

__global__ void __launch_bounds__(256, 2) gemm_tf32_single(
    const float* __restrict__ A, const float* __restrict__ B,
    const float* __restrict__ bias, float* __restrict__ C, int N, int K)
{
    gemm_core(A, B, bias, C, N, K, blockIdx.y * 128, blockIdx.x * 128);
}

__global__ void __launch_bounds__(256, 2) gemm_tf32_kv(
    const float* __restrict__ A,
    const float* __restrict__ Bk, const float* __restrict__ bk, float* __restrict__ Ck,
    const float* __restrict__ Bv, const float* __restrict__ bv, float* __restrict__ Cv,
    int N, int K)
{
    const float* B = blockIdx.z ? Bv : Bk;
    const float* bias = blockIdx.z ? bv : bk;
    float* C = blockIdx.z ? Cv : Ck;
    gemm_core(A, B, bias, C, N, K, blockIdx.y * 128, blockIdx.x * 128);
}

// ============================================================================
// RoPE in-place on g_q and g_k.
// ============================================================================
__global__ void rope_kernel(const float* __restrict__ rc)
{
    const int idx = blockIdx.x * blockDim.x + threadIdx.x;
    const int totalq = S_LEN * NH * 32;
    const int totalk = S_LEN * NKV * 32;
    if (idx < totalq) {
        const int d = idx & 31;
        const int sh = idx >> 5;
        const int h = sh & (NH - 1);
        const int s = sh >> 5;
        const float c = rc[s * HD + d];
        const float sn = rc[s * HD + 32 + d];
        float* p = g_q + ((size_t)s * NH + h) * HD;
        const float x1 = p[d], x2 = p[d + 32];
        p[d] = x1 * c - x2 * sn;
        p[d + 32] = x1 * sn + x2 * c;
    } else if (idx < totalq + totalk) {
        const int e = idx - totalq;
        const int d = e & 31;
        const int sh = e >> 5;
        const int h = sh & (NKV - 1);
        const int s = sh >> 3;
        const float c = rc[s * HD + d];
        const float sn = rc[s * HD + 32 + d];
        float* p = g_k + ((size_t)s * NKV + h) * HD;
        const float x1 = p[d], x2 = p[d + 32];
        p[d] = x1 * c - x2 * sn;
        p[d + 32] = x1 * sn + x2 * c;
    }
}

// ============================================================================
// Flash attention, TF32 tensor cores, P kept in registers.
// K/Q smem: natural round-3 layout, conflict-free 32-bit fragment LDS.
// V smem: [dim][key-slot] with keys sigma^-1-permuted within 8-groups
//   (slot = (rr>>1)|((rr&1)<<2)), so the PV b-fragment is two 32-bit
//   conflict-free reads at +lk/+lk+4 matching the C-fragment key order
//   {2lk, 2lk+1}.  V stores: thread owns dims c4+{0,16,32,48} of one key
//   -> store conflict 2-way (was 8-way).
// ============================================================================
#define FSTR 68

__global__ void __launch_bounds__(128, 4) flash_tc(const float* __restrict__ sinks)
{
    __shared__ uint32_t Ks[64 * FSTR];
    __shared__ uint32_t Vs[64 * FSTR];

    const int h = blockIdx.y;
    const int kvh = h >> 2;
    const int qt = (int)gridDim.x - 1 - (int)blockIdx.x;   // heaviest first
    const int q0 = qt * 64;
    const int tid = threadIdx.x;
    const int w = tid >> 5;
    const int l = tid & 31;
    const int l4 = l >> 2;
    const int lk = l & 3;
    const int lk2 = lk * 2;

    // ---- stage Q tile (scaled, tf32) through Ks, natural layout ----
    #pragma unroll
    for (int it = 0; it < 8; it++) {
        const int e = tid + it * 128;
        const int row = e >> 4, c4 = e & 15;
        float4 t = *(const float4*)(g_q + (size_t)(q0 + row) * (NH * HD) + h * HD + c4 * 4);
        uint32_t* p = Ks + row * FSTR + c4 * 4;
        p[0] = f2tf32(t.x * QK_SCALE);
        p[1] = f2tf32(t.y * QK_SCALE);
        p[2] = f2tf32(t.z * QK_SCALE);
        p[3] = f2tf32(t.w * QK_SCALE);
    }
    __syncthreads();

    uint32_t qf[8][4];
    #pragma unroll
    for (int kc = 0; kc < 8; kc++) {
        const uint32_t* base = Ks + (w * 16 + l4) * FSTR + kc * 8 + lk;
        qf[kc][0] = base[0];
        qf[kc][1] = base[8 * FSTR];
        qf[kc][2] = base[4];
        qf[kc][3] = base[8 * FSTR + 4];
    }

    float o[8][4];
    #pragma unroll
    for (int i = 0; i < 8; i++)
        #pragma unroll
        for (int j = 0; j < 4; j++) o[i][j] = 0.f;
    float m0 = -1e30f, m1 = -1e30f, l0 = 0.f, l1 = 0.f;

    for (int jt = 0; jt <= qt; jt++) {
        const int j0 = jt * 64;
        __syncthreads();   // qf loads / prev PV reads done before overwrite
        // ---- load K (natural) and V (dim-major, permuted key slots) ----
        #pragma unroll
        for (int it = 0; it < 8; it++) {
            const int e = tid + it * 128;
            const int row = e >> 4, c4 = e & 15;
            const size_t base = (size_t)(j0 + row) * (NKV * HD) + kvh * HD;
            float4 kv = *(const float4*)(g_k + base + c4 * 4);
            uint32_t* kp = Ks + row * FSTR + c4 * 4;
            kp[0] = f2tf32(kv.x); kp[1] = f2tf32(kv.y);
            kp[2] = f2tf32(kv.z); kp[3] = f2tf32(kv.w);
            // V: 4 scalar loads, dims c4+{0,16,32,48}; key slot permuted
            const int rr = row & 7;
            const int kslot = (row & ~7) + ((rr >> 1) | ((rr & 1) << 2));
            const float* vg = g_v + base;
            Vs[(c4 +  0) * FSTR + kslot] = f2tf32(vg[c4 +  0]);
            Vs[(c4 + 16) * FSTR + kslot] = f2tf32(vg[c4 + 16]);
            Vs[(c4 + 32) * FSTR + kslot] = f2tf32(vg[c4 + 32]);
            Vs[(c4 + 48) * FSTR + kslot] = f2tf32(vg[c4 + 48]);
        }
        __syncthreads();

        // ---- S = Q K^T (16 rows x 64 keys per warp) ----
        float c[8][4];
        #pragma unroll
        for (int i = 0; i < 8; i++)
            #pragma unroll
            for (int j = 0; j < 4; j++) c[i][j] = 0.f;
        #pragma unroll
        for (int kc = 0; kc < 8; kc++) {
            #pragma unroll
            for (int nt = 0; nt < 8; nt++) {
                uint32_t b[2];
                const uint32_t* bb = Ks + (nt * 8 + l4) * FSTR + kc * 8 + lk;
                b[0] = bb[0];
                b[1] = bb[4];
                mma_tf32(c[nt], qf[kc], b);
            }
        }

        // ---- causal mask (diagonal tile only) ----
        if (jt == qt) {
            const int row0 = w * 16 + l4, row1 = row0 + 8;
            #pragma unroll
            for (int nt = 0; nt < 8; nt++) {
                const int col = nt * 8 + lk2;
                if (col > row0)     c[nt][0] = -1e30f;
                if (col + 1 > row0) c[nt][1] = -1e30f;
                if (col > row1)     c[nt][2] = -1e30f;
                if (col + 1 > row1) c[nt][3] = -1e30f;
            }
        }

        // ---- online softmax (rows l4 and l4+8 of warp tile) ----
        float rmax0 = -1e30f, rmax1 = -1e30f;
        #pragma unroll
        for (int nt = 0; nt < 8; nt++) {
            rmax0 = fmaxf(rmax0, fmaxf(c[nt][0], c[nt][1]));
            rmax1 = fmaxf(rmax1, fmaxf(c[nt][2], c[nt][3]));
        }
        rmax0 = fmaxf(rmax0, __shfl_xor_sync(0xffffffffu, rmax0, 1));
        rmax0 = fmaxf(rmax0, __shfl_xor_sync(0xffffffffu, rmax0, 2));
        rmax1 = fmaxf(rmax1, __shfl_xor_sync(0xffffffffu, rmax1, 1));
        rmax1 = fmaxf(rmax1, __shfl_xor_sync(0xffffffffu, rmax1, 2));

        const float mn0 = fmaxf(m0, rmax0);
        const float mn1 = fmaxf(m1, rmax1);
        const float al0 = __expf(m0 - mn0);
        const float al1 = __expf(m1 - mn1);
        m0 = mn0; m1 = mn1;

        float rs0 = 0.f, rs1 = 0.f;
        #pragma unroll
        for (int nt = 0; nt < 8; nt++) {
            c[nt][0] = __expf(c[nt][0] - mn0); rs0 += c[nt][0];
            c[nt][1] = __expf(c[nt][1] - mn0); rs0 += c[nt][1];
            c[nt][2] = __expf(c[nt][2] - mn1); rs1 += c[nt][2];
            c[nt][3] = __expf(c[nt][3] - mn1); rs1 += c[nt][3];
        }
        rs0 += __shfl_xor_sync(0xffffffffu, rs0, 1);
        rs0 += __shfl_xor_sync(0xffffffffu, rs0, 2);
        rs1 += __shfl_xor_sync(0xffffffffu, rs1, 1);
        rs1 += __shfl_xor_sync(0xffffffffu, rs1, 2);
        l0 = l0 * al0 + rs0;
        l1 = l1 * al1 + rs1;

        #pragma unroll
        for (int nt = 0; nt < 8; nt++) {
            o[nt][0] *= al0; o[nt][1] *= al0;
            o[nt][2] *= al1; o[nt][3] *= al1;
        }

        // ---- O += P V : P A-fragment straight from c registers ----
        #pragma unroll
        for (int kc = 0; kc < 8; kc++) {
            uint32_t a[4];
            a[0] = f2tf32(c[kc][0]);   // (row l4,   key 2lk)   -> frag k=lk
            a[1] = f2tf32(c[kc][2]);   // (row l4+8, key 2lk)
            a[2] = f2tf32(c[kc][1]);   // (row l4,   key 2lk+1) -> frag k=lk+4
            a[3] = f2tf32(c[kc][3]);   // (row l4+8, key 2lk+1)
            #pragma unroll
            for (int nt = 0; nt < 8; nt++) {
                uint32_t b[2];
                const uint32_t* bb = Vs + (nt * 8 + l4) * FSTR + kc * 8 + lk;
                b[0] = bb[0];   // key slot lk   = key 2lk
                b[1] = bb[4];   // key slot lk+4 = key 2lk+1
                mma_tf32(o[nt], a, b);
            }
        }
    }

    // ---- epilogue: lse, sink sigmoid, normalize, store ----
    const float sk = sinks[h];
    const float lse0 = m0 + __logf(l0);
    const float lse1 = m1 + __logf(l1);
    const float w0 = (1.f / (1.f + __expf(sk - lse0))) / l0;
    const float w1 = (1.f / (1.f + __expf(sk - lse1))) / l1;
    const int row0 = q0 + w * 16 + l4;
    #pragma unroll
    for (int nt = 0; nt < 8; nt++) {
        const int col = h * HD + nt * 8 + lk2;
        float2 v0 = make_float2(o[nt][0] * w0, o[nt][1] * w0);
        float2 v1 = make_float2(o[nt][2] * w1, o[nt][3] * w1);
        *(float2*)(g_o + (size_t)row0 * (NH * HD) + col) = v0;
        *(float2*)(g_o + (size_t)(row0 + 8) * (NH * HD) + col) = v1;
    }
}

// ============================================================================
// launch
// ============================================================================
extern "C" void kernel_launch(void* const* d_in, const int* in_sizes, int n_in,
                              void* d_out, int out_size)
{
    const float* x     = (const float*)d_in[0];
    const float* rc    = (const float*)d_in[1];
    const float* wq_w  = (const float*)d_in[2];
    const float* wq_b  = (const float*)d_in[3];
    const float* wk_w  = (const float*)d_in[4];
    const float* wk_b  = (const float*)d_in[5];
    const float* wv_w  = (const float*)d_in[6];
    const float* wv_b  = (const float*)d_in[7];
    const float* wo_w  = (const float*)d_in[8];
    const float* wo_b  = (const float*)d_in[9];
    const float* sinks = (const float*)d_in[10];
    float* out = (float*)d_out;

    float *qp, *kp, *vp, *op;
    cudaGetSymbolAddress((void**)&qp, g_q);
    cudaGetSymbolAddress((void**)&kp, g_k);
    cudaGetSymbolAddress((void**)&vp, g_v);
    cudaGetSymbolAddress((void**)&op, g_o);

    // Q projection
    gemm_tf32_single<<<dim3((NH * HD) / 128, S_LEN / 128), 256>>>(x, wq_w, wq_b, qp, NH * HD, DIM);
    // fused K+V projections
    gemm_tf32_kv<<<dim3((NKV * HD) / 128, S_LEN / 128, 2), 256>>>(
        x, wk_w, wk_b, kp, wv_w, wv_b, vp, NKV * HD, DIM);

    // RoPE
    {
        const int total = S_LEN * NH * 32 + S_LEN * NKV * 32;
        rope_kernel<<<(total + 255) / 256, 256>>>(rc);
    }

    // flash attention (tf32 tensor cores, P in registers)
    flash_tc<<<dim3(S_LEN / 64, NH), 128>>>(sinks);

    // output projection
    gemm_tf32_single<<<dim3(DIM / 128, S_LEN / 128), 256>>>(op, wo_w, wo_b, out, DIM, DIM);
}

// round 6
// speedup vs baseline: 1.4279x; 1.1649x over previous
#include <cuda_runtime.h>
#include <math.h>
#include <stdint.h>

#define S_LEN 2048
#define DIM 2048
#define NH 32
#define NKV 8
#define HD 64
#define QK_SCALE 0.125f   // 1/sqrt(64)
#define NSLABS 128        // K=2048 / 16

// ---- scratch (device globals; no allocation allowed) ----
__device__ float    g_q[S_LEN * NH * HD];
__device__ float    g_k[S_LEN * NKV * HD];
__device__ float    g_v[S_LEN * NKV * HD];
__device__ uint32_t g_ot[S_LEN * NH * HD];     // attention output, tf32 bits
// pre-converted tf32 operands
__device__ uint32_t g_xt[S_LEN * DIM];
__device__ uint32_t g_wqt[NH * HD * DIM];
__device__ uint32_t g_wkt[NKV * HD * DIM];
__device__ uint32_t g_wvt[NKV * HD * DIM];
__device__ uint32_t g_wot[DIM * NH * HD];

__device__ __forceinline__ uint32_t f2tf32(float f) {
    uint32_t t;
    asm("cvt.rna.tf32.f32 %0, %1;" : "=r"(t) : "f"(f));
    return t;
}

__device__ __forceinline__ void mma_tf32(float* c, const uint32_t* a, const uint32_t* b) {
    asm volatile(
        "mma.sync.aligned.m16n8k8.row.col.f32.tf32.tf32.f32 "
        "{%0,%1,%2,%3}, {%4,%5,%6,%7}, {%8,%9}, {%0,%1,%2,%3};"
        : "+f"(c[0]), "+f"(c[1]), "+f"(c[2]), "+f"(c[3])
        : "r"(a[0]), "r"(a[1]), "r"(a[2]), "r"(a[3]), "r"(b[0]), "r"(b[1]));
}

__device__ __forceinline__ void cp16(uint32_t* smem_ptr, const uint32_t* gptr) {
    unsigned sa = (unsigned)__cvta_generic_to_shared(smem_ptr);
    asm volatile("cp.async.cg.shared.global [%0], [%1], 16;" :: "r"(sa), "l"(gptr));
}
#define CP_COMMIT() asm volatile("cp.async.commit_group;" ::: "memory")

// ============================================================================
// Pre-convert fp32 -> tf32 bits: x, wq, wk, wv, wo (single launch).
// ============================================================================
#define F4_X   1048576
#define F4_WQ  1048576
#define F4_WK  262144
#define F4_WV  262144
#define F4_WO  1048576

__global__ void conv5_kernel(const float4* __restrict__ x,
                             const float4* __restrict__ wq,
                             const float4* __restrict__ wk,
                             const float4* __restrict__ wv,
                             const float4* __restrict__ wo)
{
    int i = blockIdx.x * blockDim.x + threadIdx.x;
    const float4* s;
    uint4* d;
    int off;
    if (i < F4_X)                       { s = x;  d = (uint4*)g_xt;  off = i; }
    else if (i < F4_X + F4_WQ)          { s = wq; d = (uint4*)g_wqt; off = i - F4_X; }
    else if (i < F4_X + F4_WQ + F4_WK)  { s = wk; d = (uint4*)g_wkt; off = i - F4_X - F4_WQ; }
    else if (i < F4_X + F4_WQ + F4_WK + F4_WV)
                                        { s = wv; d = (uint4*)g_wvt; off = i - F4_X - F4_WQ - F4_WK; }
    else                                { s = wo; d = (uint4*)g_wot; off = i - F4_X - F4_WQ - F4_WK - F4_WV; }
    float4 v = s[off];
    uint4 o;
    o.x = f2tf32(v.x); o.y = f2tf32(v.y); o.z = f2tf32(v.z); o.w = f2tf32(v.w);
    d[off] = o;
}

// ============================================================================
// TF32 GEMM NT core, 4-stage cp.async pipeline, operands already tf32.
// Block 128x128x16, 8 warps, warp tile 32x64. K fixed = 2048.
// Dynamic smem: 4 stages x (As 2560 + Bs 2560) words = 80 KB.
// ============================================================================
#define SMS 20
#define STG_W (2 * 128 * SMS)   // words per stage (A+B)

__device__ __forceinline__ void gemm_core_async(
    const uint32_t* __restrict__ A, const uint32_t* __restrict__ B,
    const float* __restrict__ bias, float* __restrict__ C,
    int N, int m0, int n0, uint32_t* sm)
{
    const int tid = threadIdx.x;
    const int wid = tid >> 5;
    const int wm = wid & 3;
    const int wn = wid >> 2;
    const int l = tid & 31;
    const int l4 = l >> 2;
    const int lk = l & 3;

    const int grow = tid >> 2;        // 0..63
    const int gk4 = (tid & 3) * 4;    // word offset of this thread's float4

    const uint32_t* Ab = A + (size_t)(m0 + grow) * DIM + gk4;
    const uint32_t* Bb = B + (size_t)(n0 + grow) * DIM + gk4;

    float acc[2][8][4];
    #pragma unroll
    for (int i = 0; i < 2; i++)
        #pragma unroll
        for (int j = 0; j < 8; j++)
            #pragma unroll
            for (int q = 0; q < 4; q++) acc[i][j][q] = 0.f;

    // issue one stage's copies (4 x 16B per thread) + commit
    auto issue = [&](int slab, int slot) {
        uint32_t* dst = sm + slot * STG_W;
        const uint32_t* as = Ab + slab * 16;
        cp16(dst + grow * SMS + gk4, as);
        cp16(dst + (grow + 64) * SMS + gk4, as + (size_t)64 * DIM);
        uint32_t* bdst = dst + 128 * SMS;
        const uint32_t* bs = Bb + slab * 16;
        cp16(bdst + grow * SMS + gk4, bs);
        cp16(bdst + (grow + 64) * SMS + gk4, bs + (size_t)64 * DIM);
        CP_COMMIT();
    };

    issue(0, 0);
    issue(1, 1);
    issue(2, 2);

    for (int s = 0; s < NSLABS; s++) {
        if (s <= NSLABS - 3)      asm volatile("cp.async.wait_group 2;" ::: "memory");
        else if (s == NSLABS - 2) asm volatile("cp.async.wait_group 1;" ::: "memory");
        else                      asm volatile("cp.async.wait_group 0;" ::: "memory");
        __syncthreads();

        const uint32_t* Ac = sm + (s & 3) * STG_W;
        const uint32_t* Bc = Ac + 128 * SMS;
        #pragma unroll
        for (int k0 = 0; k0 < 16; k0 += 8) {
            uint32_t a[2][4], b[8][2];
            #pragma unroll
            for (int tm = 0; tm < 2; tm++) {
                const uint32_t* base = Ac + (wm * 32 + tm * 16 + l4) * SMS + k0 + lk;
                a[tm][0] = base[0];
                a[tm][1] = base[8 * SMS];
                a[tm][2] = base[4];
                a[tm][3] = base[8 * SMS + 4];
            }
            #pragma unroll
            for (int tn = 0; tn < 8; tn++) {
                const uint32_t* bb = Bc + (wn * 64 + tn * 8 + l4) * SMS + k0 + lk;
                b[tn][0] = bb[0];
                b[tn][1] = bb[4];
            }
            #pragma unroll
            for (int tm = 0; tm < 2; tm++)
                #pragma unroll
                for (int tn = 0; tn < 8; tn++)
                    mma_tf32(acc[tm][tn], a[tm], b[tn]);
        }

        if (s + 3 < NSLABS) issue(s + 3, (s + 3) & 3);
    }

    #pragma unroll
    for (int tm = 0; tm < 2; tm++) {
        const int row0 = m0 + wm * 32 + tm * 16 + l4;
        #pragma unroll
        for (int tn = 0; tn < 8; tn++) {
            const int col = n0 + wn * 64 + tn * 8 + lk * 2;
            const float b0 = bias[col];
            const float b1 = bias[col + 1];
            float2 v0 = make_float2(acc[tm][tn][0] + b0, acc[tm][tn][1] + b1);
            float2 v1 = make_float2(acc[tm][tn][2] + b0, acc[tm][tn][3] + b1);
            *(float2*)(C + (size_t)row0 * N + col) = v0;
            *(float2*)(C + (size_t)(row0 + 8) * N + col) = v1;
        }
    }
}

// fused Q+K+V projections: 1D grid, 256 Q blocks + 64 K + 64 V
__global__ void __launch_bounds__(256, 2) gemm_qkv(
    const float* __restrict__ wq_b, const float* __restrict__ wk_b,
    const float* __restrict__ wv_b)
{
    extern __shared__ uint32_t sm[];
    int id = blockIdx.x;
    if (id < 256) {
        gemm_core_async(g_xt, g_wqt, wq_b, g_q, NH * HD, (id >> 4) * 128, (id & 15) * 128, sm);
    } else if (id < 320) {
        id -= 256;
        gemm_core_async(g_xt, g_wkt, wk_b, g_k, NKV * HD, (id >> 2) * 128, (id & 3) * 128, sm);
    } else {
        id -= 320;
        gemm_core_async(g_xt, g_wvt, wv_b, g_v, NKV * HD, (id >> 2) * 128, (id & 3) * 128, sm);
    }
}

// output projection: A = g_ot (tf32), B = g_wot
__global__ void __launch_bounds__(256, 2) gemm_o(
    const float* __restrict__ wo_b, float* __restrict__ out)
{
    extern __shared__ uint32_t sm[];
    const int id = blockIdx.x;
    gemm_core_async(g_ot, g_wot, wo_b, out, DIM, (id >> 4) * 128, (id & 15) * 128, sm);
}

// ============================================================================
// RoPE in-place on g_q and g_k.
// ============================================================================
__global__ void rope_kernel(const float* __restrict__ rc)
{
    const int idx = blockIdx.x * blockDim.x + threadIdx.x;
    const int totalq = S_LEN * NH * 32;
    const int totalk = S_LEN * NKV * 32;
    if (idx < totalq) {
        const int d = idx & 31;
        const int sh = idx >> 5;
        const int h = sh & (NH - 1);
        const int s = sh >> 5;
        const float c = rc[s * HD + d];
        const float sn = rc[s * HD + 32 + d];
        float* p = g_q + ((size_t)s * NH + h) * HD;
        const float x1 = p[d], x2 = p[d + 32];
        p[d] = x1 * c - x2 * sn;
        p[d + 32] = x1 * sn + x2 * c;
    } else if (idx < totalq + totalk) {
        const int e = idx - totalq;
        const int d = e & 31;
        const int sh = e >> 5;
        const int h = sh & (NKV - 1);
        const int s = sh >> 3;
        const float c = rc[s * HD + d];
        const float sn = rc[s * HD + 32 + d];
        float* p = g_k + ((size_t)s * NKV + h) * HD;
        const float x1 = p[d], x2 = p[d + 32];
        p[d] = x1 * c - x2 * sn;
        p[d + 32] = x1 * sn + x2 * c;
    }
}

// ============================================================================
// Flash attention, TF32 tensor cores, P in registers (round-5 layout).
// Epilogue writes tf32 bits to g_ot for the O projection.
// ============================================================================
#define FSTR 68

__global__ void __launch_bounds__(128, 4) flash_tc(const float* __restrict__ sinks)
{
    __shared__ uint32_t Ks[64 * FSTR];
    __shared__ uint32_t Vs[64 * FSTR];

    const int h = blockIdx.y;
    const int kvh = h >> 2;
    const int qt = (int)gridDim.x - 1 - (int)blockIdx.x;   // heaviest first
    const int q0 = qt * 64;
    const int tid = threadIdx.x;
    const int w = tid >> 5;
    const int l = tid & 31;
    const int l4 = l >> 2;
    const int lk = l & 3;
    const int lk2 = lk * 2;

    // ---- stage Q tile (scaled, tf32) through Ks ----
    #pragma unroll
    for (int it = 0; it < 8; it++) {
        const int e = tid + it * 128;
        const int row = e >> 4, c4 = e & 15;
        float4 t = *(const float4*)(g_q + (size_t)(q0 + row) * (NH * HD) + h * HD + c4 * 4);
        uint32_t* p = Ks + row * FSTR + c4 * 4;
        p[0] = f2tf32(t.x * QK_SCALE);
        p[1] = f2tf32(t.y * QK_SCALE);
        p[2] = f2tf32(t.z * QK_SCALE);
        p[3] = f2tf32(t.w * QK_SCALE);
    }
    __syncthreads();

    uint32_t qf[8][4];
    #pragma unroll
    for (int kc = 0; kc < 8; kc++) {
        const uint32_t* base = Ks + (w * 16 + l4) * FSTR + kc * 8 + lk;
        qf[kc][0] = base[0];
        qf[kc][1] = base[8 * FSTR];
        qf[kc][2] = base[4];
        qf[kc][3] = base[8 * FSTR + 4];
    }

    float o[8][4];
    #pragma unroll
    for (int i = 0; i < 8; i++)
        #pragma unroll
        for (int j = 0; j < 4; j++) o[i][j] = 0.f;
    float m0 = -1e30f, m1 = -1e30f, l0 = 0.f, l1 = 0.f;

    for (int jt = 0; jt <= qt; jt++) {
        const int j0 = jt * 64;
        __syncthreads();
        // ---- load K (natural) and V (dim-major, permuted key slots) ----
        #pragma unroll
        for (int it = 0; it < 8; it++) {
            const int e = tid + it * 128;
            const int row = e >> 4, c4 = e & 15;
            const size_t base = (size_t)(j0 + row) * (NKV * HD) + kvh * HD;
            float4 kv = *(const float4*)(g_k + base + c4 * 4);
            uint32_t* kp = Ks + row * FSTR + c4 * 4;
            kp[0] = f2tf32(kv.x); kp[1] = f2tf32(kv.y);
            kp[2] = f2tf32(kv.z); kp[3] = f2tf32(kv.w);
            const int rr = row & 7;
            const int kslot = (row & ~7) + ((rr >> 1) | ((rr & 1) << 2));
            const float* vg = g_v + base;
            Vs[(c4 +  0) * FSTR + kslot] = f2tf32(vg[c4 +  0]);
            Vs[(c4 + 16) * FSTR + kslot] = f2tf32(vg[c4 + 16]);
            Vs[(c4 + 32) * FSTR + kslot] = f2tf32(vg[c4 + 32]);
            Vs[(c4 + 48) * FSTR + kslot] = f2tf32(vg[c4 + 48]);
        }
        __syncthreads();

        // ---- S = Q K^T ----
        float c[8][4];
        #pragma unroll
        for (int i = 0; i < 8; i++)
            #pragma unroll
            for (int j = 0; j < 4; j++) c[i][j] = 0.f;
        #pragma unroll
        for (int kc = 0; kc < 8; kc++) {
            #pragma unroll
            for (int nt = 0; nt < 8; nt++) {
                uint32_t b[2];
                const uint32_t* bb = Ks + (nt * 8 + l4) * FSTR + kc * 8 + lk;
                b[0] = bb[0];
                b[1] = bb[4];
                mma_tf32(c[nt], qf[kc], b);
            }
        }

        // ---- causal mask (diagonal tile only) ----
        if (jt == qt) {
            const int row0 = w * 16 + l4, row1 = row0 + 8;
            #pragma unroll
            for (int nt = 0; nt < 8; nt++) {
                const int col = nt * 8 + lk2;
                if (col > row0)     c[nt][0] = -1e30f;
                if (col + 1 > row0) c[nt][1] = -1e30f;
                if (col > row1)     c[nt][2] = -1e30f;
                if (col + 1 > row1) c[nt][3] = -1e30f;
            }
        }

        // ---- online softmax ----
        float rmax0 = -1e30f, rmax1 = -1e30f;
        #pragma unroll
        for (int nt = 0; nt < 8; nt++) {
            rmax0 = fmaxf(rmax0, fmaxf(c[nt][0], c[nt][1]));
            rmax1 = fmaxf(rmax1, fmaxf(c[nt][2], c[nt][3]));
        }
        rmax0 = fmaxf(rmax0, __shfl_xor_sync(0xffffffffu, rmax0, 1));
        rmax0 = fmaxf(rmax0, __shfl_xor_sync(0xffffffffu, rmax0, 2));
        rmax1 = fmaxf(rmax1, __shfl_xor_sync(0xffffffffu, rmax1, 1));
        rmax1 = fmaxf(rmax1, __shfl_xor_sync(0xffffffffu, rmax1, 2));

        const float mn0 = fmaxf(m0, rmax0);
        const float mn1 = fmaxf(m1, rmax1);
        const float al0 = __expf(m0 - mn0);
        const float al1 = __expf(m1 - mn1);
        m0 = mn0; m1 = mn1;

        float rs0 = 0.f, rs1 = 0.f;
        #pragma unroll
        for (int nt = 0; nt < 8; nt++) {
            c[nt][0] = __expf(c[nt][0] - mn0); rs0 += c[nt][0];
            c[nt][1] = __expf(c[nt][1] - mn0); rs0 += c[nt][1];
            c[nt][2] = __expf(c[nt][2] - mn1); rs1 += c[nt][2];
            c[nt][3] = __expf(c[nt][3] - mn1); rs1 += c[nt][3];
        }
        rs0 += __shfl_xor_sync(0xffffffffu, rs0, 1);
        rs0 += __shfl_xor_sync(0xffffffffu, rs0, 2);
        rs1 += __shfl_xor_sync(0xffffffffu, rs1, 1);
        rs1 += __shfl_xor_sync(0xffffffffu, rs1, 2);
        l0 = l0 * al0 + rs0;
        l1 = l1 * al1 + rs1;

        #pragma unroll
        for (int nt = 0; nt < 8; nt++) {
            o[nt][0] *= al0; o[nt][1] *= al0;
            o[nt][2] *= al1; o[nt][3] *= al1;
        }

        // ---- O += P V : P A-fragment straight from c registers ----
        #pragma unroll
        for (int kc = 0; kc < 8; kc++) {
            uint32_t a[4];
            a[0] = f2tf32(c[kc][0]);
            a[1] = f2tf32(c[kc][2]);
            a[2] = f2tf32(c[kc][1]);
            a[3] = f2tf32(c[kc][3]);
            #pragma unroll
            for (int nt = 0; nt < 8; nt++) {
                uint32_t b[2];
                const uint32_t* bb = Vs + (nt * 8 + l4) * FSTR + kc * 8 + lk;
                b[0] = bb[0];
                b[1] = bb[4];
                mma_tf32(o[nt], a, b);
            }
        }
    }

    // ---- epilogue: lse, sink sigmoid, normalize, store tf32 bits ----
    const float sk = sinks[h];
    const float lse0 = m0 + __logf(l0);
    const float lse1 = m1 + __logf(l1);
    const float w0 = (1.f / (1.f + __expf(sk - lse0))) / l0;
    const float w1 = (1.f / (1.f + __expf(sk - lse1))) / l1;
    const int row0 = q0 + w * 16 + l4;
    #pragma unroll
    for (int nt = 0; nt < 8; nt++) {
        const int col = h * HD + nt * 8 + lk2;
        uint2 v0 = make_uint2(f2tf32(o[nt][0] * w0), f2tf32(o[nt][1] * w0));
        uint2 v1 = make_uint2(f2tf32(o[nt][2] * w1), f2tf32(o[nt][3] * w1));
        *(uint2*)(g_ot + (size_t)row0 * (NH * HD) + col) = v0;
        *(uint2*)(g_ot + (size_t)(row0 + 8) * (NH * HD) + col) = v1;
    }
}

// ============================================================================
// launch
// ============================================================================
extern "C" void kernel_launch(void* const* d_in, const int* in_sizes, int n_in,
                              void* d_out, int out_size)
{
    const float* x     = (const float*)d_in[0];
    const float* rc    = (const float*)d_in[1];
    const float* wq_w  = (const float*)d_in[2];
    const float* wq_b  = (const float*)d_in[3];
    const float* wk_w  = (const float*)d_in[4];
    const float* wk_b  = (const float*)d_in[5];
    const float* wv_w  = (const float*)d_in[6];
    const float* wv_b  = (const float*)d_in[7];
    const float* wo_w  = (const float*)d_in[8];
    const float* wo_b  = (const float*)d_in[9];
    const float* sinks = (const float*)d_in[10];
    float* out = (float*)d_out;

    const int gemm_smem = 4 * STG_W * 4;   // 80 KB
    cudaFuncSetAttribute(gemm_qkv, cudaFuncAttributeMaxDynamicSharedMemorySize, gemm_smem);
    cudaFuncSetAttribute(gemm_o,   cudaFuncAttributeMaxDynamicSharedMemorySize, gemm_smem);

    // 1. pre-convert x + weights to tf32
    conv5_kernel<<<(F4_X + F4_WQ + F4_WK + F4_WV + F4_WO) / 256, 256>>>(
        (const float4*)x, (const float4*)wq_w, (const float4*)wk_w,
        (const float4*)wv_w, (const float4*)wo_w);

    // 2. fused Q+K+V projections
    gemm_qkv<<<384, 256, gemm_smem>>>(wq_b, wk_b, wv_b);

    // 3. RoPE
    {
        const int total = S_LEN * NH * 32 + S_LEN * NKV * 32;
        rope_kernel<<<(total + 255) / 256, 256>>>(rc);
    }

    // 4. flash attention
    flash_tc<<<dim3(S_LEN / 64, NH), 128>>>(sinks);

    // 5. output projection
    gemm_o<<<256, 256, gemm_smem>>>(wo_b, out);
}

// round 7
// speedup vs baseline: 1.6668x; 1.1673x over previous
#include <cuda_runtime.h>
#include <math.h>
#include <stdint.h>

#define S_LEN 2048
#define DIM 2048
#define NH 32
#define NKV 8
#define HD 64
#define QK_SCALE 0.125f   // 1/sqrt(64)
#define NSLABS 128        // K=2048 / 16

// ---- scratch (device globals; no allocation allowed) ----
__device__ float    g_q[S_LEN * NH * HD];      // Q proj (pre-RoPE, fp32)
__device__ float    g_k[S_LEN * NKV * HD];     // K proj (pre-RoPE, fp32)
__device__ uint32_t g_qt[S_LEN * NH * HD];     // Q RoPE'd, scaled, tf32
__device__ uint32_t g_kt[S_LEN * NKV * HD];    // K RoPE'd, tf32
__device__ uint32_t g_vt[NKV * HD * S_LEN];    // V transposed [dim][seq], tf32
__device__ uint32_t g_ot[S_LEN * NH * HD];     // attention output, tf32
// pre-converted tf32 GEMM operands
__device__ uint32_t g_xt[S_LEN * DIM];
__device__ uint32_t g_wqt[NH * HD * DIM];
__device__ uint32_t g_wkt[NKV * HD * DIM];
__device__ uint32_t g_wvt[NKV * HD * DIM];
__device__ uint32_t g_wot[DIM * NH * HD];

__device__ __forceinline__ uint32_t f2tf32(float f) {
    uint32_t t;
    asm("cvt.rna.tf32.f32 %0, %1;" : "=r"(t) : "f"(f));
    return t;
}

__device__ __forceinline__ void mma_tf32(float* c, const uint32_t* a, const uint32_t* b) {
    asm volatile(
        "mma.sync.aligned.m16n8k8.row.col.f32.tf32.tf32.f32 "
        "{%0,%1,%2,%3}, {%4,%5,%6,%7}, {%8,%9}, {%0,%1,%2,%3};"
        : "+f"(c[0]), "+f"(c[1]), "+f"(c[2]), "+f"(c[3])
        : "r"(a[0]), "r"(a[1]), "r"(a[2]), "r"(a[3]), "r"(b[0]), "r"(b[1]));
}

__device__ __forceinline__ void cp16(uint32_t* smem_ptr, const uint32_t* gptr) {
    unsigned sa = (unsigned)__cvta_generic_to_shared(smem_ptr);
    asm volatile("cp.async.cg.shared.global [%0], [%1], 16;" :: "r"(sa), "l"(gptr));
}
#define CP_COMMIT() asm volatile("cp.async.commit_group;" ::: "memory")
#define CP_WAIT0()  asm volatile("cp.async.wait_group 0;" ::: "memory")

// ============================================================================
// Pre-convert fp32 -> tf32 bits: x, wq, wk, wv, wo (single launch).
// ============================================================================
#define F4_X   1048576
#define F4_WQ  1048576
#define F4_WK  262144
#define F4_WV  262144
#define F4_WO  1048576

__global__ void conv5_kernel(const float4* __restrict__ x,
                             const float4* __restrict__ wq,
                             const float4* __restrict__ wk,
                             const float4* __restrict__ wv,
                             const float4* __restrict__ wo)
{
    int i = blockIdx.x * blockDim.x + threadIdx.x;
    const float4* s;
    uint4* d;
    int off;
    if (i < F4_X)                       { s = x;  d = (uint4*)g_xt;  off = i; }
    else if (i < F4_X + F4_WQ)          { s = wq; d = (uint4*)g_wqt; off = i - F4_X; }
    else if (i < F4_X + F4_WQ + F4_WK)  { s = wk; d = (uint4*)g_wkt; off = i - F4_X - F4_WQ; }
    else if (i < F4_X + F4_WQ + F4_WK + F4_WV)
                                        { s = wv; d = (uint4*)g_wvt; off = i - F4_X - F4_WQ - F4_WK; }
    else                                { s = wo; d = (uint4*)g_wot; off = i - F4_X - F4_WQ - F4_WK - F4_WV; }
    float4 v = s[off];
    uint4 o;
    o.x = f2tf32(v.x); o.y = f2tf32(v.y); o.z = f2tf32(v.z); o.w = f2tf32(v.w);
    d[off] = o;
}

// ============================================================================
// TF32 GEMM NT core, 4-stage cp.async pipeline, stride-24 smem:
// 24 mod 32 == 8*3 -> 64-bit fragment loads are bank-conflict-free.
// k-remap: frag slot lk <-> element k0+2lk, lk+4 <-> k0+2lk+1 (both operands).
// EPI: 0 = fp32 C + bias; 1 = V mode (tf32 bits, transposed [dim][seq]).
// ============================================================================
#define SMS 24
#define A_W (128 * SMS)         // 3072 words
#define STG_W (2 * 128 * SMS)   // 6144 words per stage

template <int EPI>
__device__ __forceinline__ void gemm_core_async(
    const uint32_t* __restrict__ A, const uint32_t* __restrict__ B,
    const float* __restrict__ bias, float* __restrict__ C, uint32_t* __restrict__ Ct,
    int N, int m0, int n0, uint32_t* sm)
{
    const int tid = threadIdx.x;
    const int wid = tid >> 5;
    const int wm = wid & 3;
    const int wn = wid >> 2;
    const int l = tid & 31;
    const int l4 = l >> 2;
    const int lk2 = (l & 3) * 2;

    const int grow = tid >> 2;        // 0..63
    const int gk4 = (tid & 3) * 4;    // word offset of this thread's 16B chunk

    const uint32_t* Ab = A + (size_t)(m0 + grow) * DIM + gk4;
    const uint32_t* Bb = B + (size_t)(n0 + grow) * DIM + gk4;

    float acc[2][8][4];
    #pragma unroll
    for (int i = 0; i < 2; i++)
        #pragma unroll
        for (int j = 0; j < 8; j++)
            #pragma unroll
            for (int q = 0; q < 4; q++) acc[i][j][q] = 0.f;

    auto issue = [&](int slab, int slot) {
        uint32_t* dst = sm + slot * STG_W;
        const uint32_t* as = Ab + slab * 16;
        cp16(dst + grow * SMS + gk4, as);
        cp16(dst + (grow + 64) * SMS + gk4, as + (size_t)64 * DIM);
        uint32_t* bdst = dst + A_W;
        const uint32_t* bs = Bb + slab * 16;
        cp16(bdst + grow * SMS + gk4, bs);
        cp16(bdst + (grow + 64) * SMS + gk4, bs + (size_t)64 * DIM);
        CP_COMMIT();
    };

    issue(0, 0);
    issue(1, 1);
    issue(2, 2);

    for (int s = 0; s < NSLABS; s++) {
        if (s <= NSLABS - 3)      asm volatile("cp.async.wait_group 2;" ::: "memory");
        else if (s == NSLABS - 2) asm volatile("cp.async.wait_group 1;" ::: "memory");
        else                      asm volatile("cp.async.wait_group 0;" ::: "memory");
        __syncthreads();

        const uint32_t* Ac = sm + (s & 3) * STG_W;
        const uint32_t* Bc = Ac + A_W;
        #pragma unroll
        for (int k0 = 0; k0 < 16; k0 += 8) {
            uint32_t a[2][4], b[8][2];
            #pragma unroll
            for (int tm = 0; tm < 2; tm++) {
                const uint32_t* base = Ac + (wm * 32 + tm * 16 + l4) * SMS + k0 + lk2;
                const uint2 t0 = *(const uint2*)(base);
                const uint2 t1 = *(const uint2*)(base + 8 * SMS);
                a[tm][0] = t0.x; a[tm][1] = t1.x;
                a[tm][2] = t0.y; a[tm][3] = t1.y;
            }
            #pragma unroll
            for (int tn = 0; tn < 8; tn++) {
                const uint2 t = *(const uint2*)(Bc + (wn * 64 + tn * 8 + l4) * SMS + k0 + lk2);
                b[tn][0] = t.x; b[tn][1] = t.y;
            }
            #pragma unroll
            for (int tm = 0; tm < 2; tm++)
                #pragma unroll
                for (int tn = 0; tn < 8; tn++)
                    mma_tf32(acc[tm][tn], a[tm], b[tn]);
        }

        if (s + 3 < NSLABS) issue(s + 3, (s + 3) & 3);
    }

    #pragma unroll
    for (int tm = 0; tm < 2; tm++) {
        const int row0 = m0 + wm * 32 + tm * 16 + l4;
        #pragma unroll
        for (int tn = 0; tn < 8; tn++) {
            const int col = n0 + wn * 64 + tn * 8 + lk2;
            const float b0 = bias[col];
            const float b1 = bias[col + 1];
            if (EPI == 0) {
                float2 v0 = make_float2(acc[tm][tn][0] + b0, acc[tm][tn][1] + b1);
                float2 v1 = make_float2(acc[tm][tn][2] + b0, acc[tm][tn][3] + b1);
                *(float2*)(C + (size_t)row0 * N + col) = v0;
                *(float2*)(C + (size_t)(row0 + 8) * N + col) = v1;
            } else {
                // V mode: transposed [dim][seq], tf32 bits
                Ct[(size_t)col * S_LEN + row0]           = f2tf32(acc[tm][tn][0] + b0);
                Ct[(size_t)(col + 1) * S_LEN + row0]     = f2tf32(acc[tm][tn][1] + b1);
                Ct[(size_t)col * S_LEN + row0 + 8]       = f2tf32(acc[tm][tn][2] + b0);
                Ct[(size_t)(col + 1) * S_LEN + row0 + 8] = f2tf32(acc[tm][tn][3] + b1);
            }
        }
    }
}

// fused Q+K+V projections: 256 Q blocks + 64 K + 64 V
__global__ void __launch_bounds__(256, 2) gemm_qkv(
    const float* __restrict__ wq_b, const float* __restrict__ wk_b,
    const float* __restrict__ wv_b)
{
    extern __shared__ uint32_t sm[];
    int id = blockIdx.x;
    if (id < 256) {
        gemm_core_async<0>(g_xt, g_wqt, wq_b, g_q, nullptr, NH * HD, (id >> 4) * 128, (id & 15) * 128, sm);
    } else if (id < 320) {
        id -= 256;
        gemm_core_async<0>(g_xt, g_wkt, wk_b, g_k, nullptr, NKV * HD, (id >> 2) * 128, (id & 3) * 128, sm);
    } else {
        id -= 320;
        gemm_core_async<1>(g_xt, g_wvt, wv_b, nullptr, g_vt, NKV * HD, (id >> 2) * 128, (id & 3) * 128, sm);
    }
}

__global__ void __launch_bounds__(256, 2) gemm_o(
    const float* __restrict__ wo_b, float* __restrict__ out)
{
    extern __shared__ uint32_t sm[];
    const int id = blockIdx.x;
    gemm_core_async<0>(g_ot, g_wot, wo_b, out, nullptr, DIM, (id >> 4) * 128, (id & 15) * 128, sm);
}

// ============================================================================
// RoPE: read fp32 g_q/g_k, rotate, write tf32 g_qt (pre-scaled) / g_kt.
// ============================================================================
__global__ void rope_kernel(const float* __restrict__ rc)
{
    const int idx = blockIdx.x * blockDim.x + threadIdx.x;
    const int totalq = S_LEN * NH * 32;
    const int totalk = S_LEN * NKV * 32;
    if (idx < totalq) {
        const int d = idx & 31;
        const int sh = idx >> 5;
        const int h = sh & (NH - 1);
        const int s = sh >> 5;
        const float c = rc[s * HD + d];
        const float sn = rc[s * HD + 32 + d];
        const size_t base = ((size_t)s * NH + h) * HD;
        const float x1 = g_q[base + d], x2 = g_q[base + d + 32];
        g_qt[base + d]      = f2tf32((x1 * c - x2 * sn) * QK_SCALE);
        g_qt[base + d + 32] = f2tf32((x1 * sn + x2 * c) * QK_SCALE);
    } else if (idx < totalq + totalk) {
        const int e = idx - totalq;
        const int d = e & 31;
        const int sh = e >> 5;
        const int h = sh & (NKV - 1);
        const int s = sh >> 3;
        const float c = rc[s * HD + d];
        const float sn = rc[s * HD + 32 + d];
        const size_t base = ((size_t)s * NKV + h) * HD;
        const float x1 = g_k[base + d], x2 = g_k[base + d + 32];
        g_kt[base + d]      = f2tf32(x1 * c - x2 * sn);
        g_kt[base + d + 32] = f2tf32(x1 * sn + x2 * c);
    }
}

// ============================================================================
// Flash attention, TF32 tensor cores, P in registers.
// All operands pre-converted tf32 in gmem -> staging is pure cp.async,
// double-buffered (copy of tile jt+1 overlaps compute of tile jt).
// Stride 72 (== 8 mod 32) -> all 64-bit fragment LDS are conflict-free.
// k-remap (frag slot lk <-> element 2lk) applied to both mma operands.
// ============================================================================
#define FSTR 72
#define FTILE (64 * FSTR)   // words per tile buffer

__global__ void __launch_bounds__(128, 3) flash_tc(const float* __restrict__ sinks)
{
    extern __shared__ uint32_t fsm[];
    // layout: [K0][V0][K1][V1]
    const int h = blockIdx.y;
    const int kvh = h >> 2;
    const int qt = (int)gridDim.x - 1 - (int)blockIdx.x;   // heaviest first
    const int q0 = qt * 64;
    const int tid = threadIdx.x;
    const int w = tid >> 5;
    const int l = tid & 31;
    const int l4 = l >> 2;
    const int lk = l & 3;
    const int lk2 = lk * 2;

    // ---- stage Q tile via cp.async into buffer 0 (reused for K later) ----
    #pragma unroll
    for (int it = 0; it < 8; it++) {
        const int e = tid + it * 128;
        const int row = e >> 4, ch = e & 15;
        cp16(fsm + row * FSTR + ch * 4,
             g_qt + (size_t)(q0 + row) * (NH * HD) + h * HD + ch * 4);
    }
    CP_COMMIT();
    CP_WAIT0();
    __syncthreads();

    uint32_t qf[8][4];
    #pragma unroll
    for (int kc = 0; kc < 8; kc++) {
        const uint32_t* base = fsm + (w * 16 + l4) * FSTR + kc * 8 + lk2;
        const uint2 t0 = *(const uint2*)(base);
        const uint2 t1 = *(const uint2*)(base + 8 * FSTR);
        qf[kc][0] = t0.x; qf[kc][1] = t1.x;
        qf[kc][2] = t0.y; qf[kc][3] = t1.y;
    }
    __syncthreads();   // all qf reads done before K tile overwrites buffer 0

    // per-tile K+V staging: 16 cp16/thread
    auto issueKV = [&](int jt, int slot) {
        uint32_t* Kb = fsm + slot * 2 * FTILE;
        uint32_t* Vb = Kb + FTILE;
        const int j0 = jt * 64;
        #pragma unroll
        for (int it = 0; it < 8; it++) {
            const int e = tid + it * 128;
            const int row = e >> 4, ch = e & 15;
            cp16(Kb + row * FSTR + ch * 4,
                 g_kt + (size_t)(j0 + row) * (NKV * HD) + kvh * HD + ch * 4);
            cp16(Vb + row * FSTR + ch * 4,
                 g_vt + (size_t)(kvh * HD + row) * S_LEN + j0 + ch * 4);
        }
        CP_COMMIT();
    };

    float o[8][4];
    #pragma unroll
    for (int i = 0; i < 8; i++)
        #pragma unroll
        for (int j = 0; j < 4; j++) o[i][j] = 0.f;
    float m0 = -1e30f, m1 = -1e30f, l0 = 0.f, l1 = 0.f;

    issueKV(0, 0);

    for (int jt = 0; jt <= qt; jt++) {
        CP_WAIT0();
        __syncthreads();
        if (jt < qt) issueKV(jt + 1, (jt + 1) & 1);

        const uint32_t* Kb = fsm + (jt & 1) * 2 * FTILE;
        const uint32_t* Vb = Kb + FTILE;

        // ---- S = Q K^T ----
        float c[8][4];
        #pragma unroll
        for (int i = 0; i < 8; i++)
            #pragma unroll
            for (int j = 0; j < 4; j++) c[i][j] = 0.f;
        #pragma unroll
        for (int kc = 0; kc < 8; kc++) {
            #pragma unroll
            for (int nt = 0; nt < 8; nt++) {
                uint32_t b[2];
                const uint2 t = *(const uint2*)(Kb + (nt * 8 + l4) * FSTR + kc * 8 + lk2);
                b[0] = t.x; b[1] = t.y;
                mma_tf32(c[nt], qf[kc], b);
            }
        }

        // ---- causal mask (diagonal tile only) ----
        if (jt == qt) {
            const int row0 = w * 16 + l4, row1 = row0 + 8;
            #pragma unroll
            for (int nt = 0; nt < 8; nt++) {
                const int col = nt * 8 + lk2;
                if (col > row0)     c[nt][0] = -1e30f;
                if (col + 1 > row0) c[nt][1] = -1e30f;
                if (col > row1)     c[nt][2] = -1e30f;
                if (col + 1 > row1) c[nt][3] = -1e30f;
            }
        }

        // ---- online softmax ----
        float rmax0 = -1e30f, rmax1 = -1e30f;
        #pragma unroll
        for (int nt = 0; nt < 8; nt++) {
            rmax0 = fmaxf(rmax0, fmaxf(c[nt][0], c[nt][1]));
            rmax1 = fmaxf(rmax1, fmaxf(c[nt][2], c[nt][3]));
        }
        rmax0 = fmaxf(rmax0, __shfl_xor_sync(0xffffffffu, rmax0, 1));
        rmax0 = fmaxf(rmax0, __shfl_xor_sync(0xffffffffu, rmax0, 2));
        rmax1 = fmaxf(rmax1, __shfl_xor_sync(0xffffffffu, rmax1, 1));
        rmax1 = fmaxf(rmax1, __shfl_xor_sync(0xffffffffu, rmax1, 2));

        const float mn0 = fmaxf(m0, rmax0);
        const float mn1 = fmaxf(m1, rmax1);
        const float al0 = __expf(m0 - mn0);
        const float al1 = __expf(m1 - mn1);
        m0 = mn0; m1 = mn1;

        float rs0 = 0.f, rs1 = 0.f;
        #pragma unroll
        for (int nt = 0; nt < 8; nt++) {
            c[nt][0] = __expf(c[nt][0] - mn0); rs0 += c[nt][0];
            c[nt][1] = __expf(c[nt][1] - mn0); rs0 += c[nt][1];
            c[nt][2] = __expf(c[nt][2] - mn1); rs1 += c[nt][2];
            c[nt][3] = __expf(c[nt][3] - mn1); rs1 += c[nt][3];
        }
        rs0 += __shfl_xor_sync(0xffffffffu, rs0, 1);
        rs0 += __shfl_xor_sync(0xffffffffu, rs0, 2);
        rs1 += __shfl_xor_sync(0xffffffffu, rs1, 1);
        rs1 += __shfl_xor_sync(0xffffffffu, rs1, 2);
        l0 = l0 * al0 + rs0;
        l1 = l1 * al1 + rs1;

        #pragma unroll
        for (int nt = 0; nt < 8; nt++) {
            o[nt][0] *= al0; o[nt][1] *= al0;
            o[nt][2] *= al1; o[nt][3] *= al1;
        }

        // ---- O += P V : P A-fragment straight from c registers ----
        #pragma unroll
        for (int kc = 0; kc < 8; kc++) {
            uint32_t a[4];
            a[0] = f2tf32(c[kc][0]);   // key 2lk   -> frag slot lk
            a[1] = f2tf32(c[kc][2]);
            a[2] = f2tf32(c[kc][1]);   // key 2lk+1 -> frag slot lk+4
            a[3] = f2tf32(c[kc][3]);
            #pragma unroll
            for (int nt = 0; nt < 8; nt++) {
                uint32_t b[2];
                const uint2 t = *(const uint2*)(Vb + (nt * 8 + l4) * FSTR + kc * 8 + lk2);
                b[0] = t.x; b[1] = t.y;
                mma_tf32(o[nt], a, b);
            }
        }
        __syncthreads();   // reads of this tile done before next overwrite
    }

    // ---- epilogue: lse, sink sigmoid, normalize, store tf32 bits ----
    const float sk = sinks[h];
    const float lse0 = m0 + __logf(l0);
    const float lse1 = m1 + __logf(l1);
    const float w0 = (1.f / (1.f + __expf(sk - lse0))) / l0;
    const float w1 = (1.f / (1.f + __expf(sk - lse1))) / l1;
    const int row0 = q0 + w * 16 + l4;
    #pragma unroll
    for (int nt = 0; nt < 8; nt++) {
        const int col = h * HD + nt * 8 + lk2;
        uint2 v0 = make_uint2(f2tf32(o[nt][0] * w0), f2tf32(o[nt][1] * w0));
        uint2 v1 = make_uint2(f2tf32(o[nt][2] * w1), f2tf32(o[nt][3] * w1));
        *(uint2*)(g_ot + (size_t)row0 * (NH * HD) + col) = v0;
        *(uint2*)(g_ot + (size_t)(row0 + 8) * (NH * HD) + col) = v1;
    }
}

// ============================================================================
// launch
// ============================================================================
extern "C" void kernel_launch(void* const* d_in, const int* in_sizes, int n_in,
                              void* d_out, int out_size)
{
    const float* x     = (const float*)d_in[0];
    const float* rc    = (const float*)d_in[1];
    const float* wq_w  = (const float*)d_in[2];
    const float* wq_b  = (const float*)d_in[3];
    const float* wk_w  = (const float*)d_in[4];
    const float* wk_b  = (const float*)d_in[5];
    const float* wv_w  = (const float*)d_in[6];
    const float* wv_b  = (const float*)d_in[7];
    const float* wo_w  = (const float*)d_in[8];
    const float* wo_b  = (const float*)d_in[9];
    const float* sinks = (const float*)d_in[10];
    float* out = (float*)d_out;

    const int gemm_smem  = 4 * STG_W * 4;     // 96 KB
    const int flash_smem = 4 * FTILE * 4;     // 72 KB (2 stages x K,V)
    cudaFuncSetAttribute(gemm_qkv, cudaFuncAttributeMaxDynamicSharedMemorySize, gemm_smem);
    cudaFuncSetAttribute(gemm_o,   cudaFuncAttributeMaxDynamicSharedMemorySize, gemm_smem);
    cudaFuncSetAttribute(flash_tc, cudaFuncAttributeMaxDynamicSharedMemorySize, flash_smem);

    // 1. pre-convert x + weights to tf32
    conv5_kernel<<<(F4_X + F4_WQ + F4_WK + F4_WV + F4_WO) / 256, 256>>>(
        (const float4*)x, (const float4*)wq_w, (const float4*)wk_w,
        (const float4*)wv_w, (const float4*)wo_w);

    // 2. fused Q+K+V projections (V written transposed tf32)
    gemm_qkv<<<384, 256, gemm_smem>>>(wq_b, wk_b, wv_b);

    // 3. RoPE -> tf32 operand buffers
    {
        const int total = S_LEN * NH * 32 + S_LEN * NKV * 32;
        rope_kernel<<<(total + 255) / 256, 256>>>(rc);
    }

    // 4. flash attention
    flash_tc<<<dim3(S_LEN / 64, NH), 128, flash_smem>>>(sinks);

    // 5. output projection
    gemm_o<<<256, 256, gemm_smem>>>(wo_b, out);
}

// round 10
// speedup vs baseline: 2.5995x; 1.5596x over previous
#include <cuda_runtime.h>
#include <cuda_fp16.h>
#include <math.h>
#include <stdint.h>

#define S_LEN 2048
#define DIM 2048
#define NH 32
#define NKV 8
#define HD 64
#define QK_SCALE 0.125f
#define GK 2048
#define NSLAB 64           // K=2048 / 32

// ---- scratch (device globals; no allocation allowed) ----
__device__ float  g_q[S_LEN * NH * HD];     // Q proj (pre-RoPE, fp32)
__device__ float  g_k[S_LEN * NKV * HD];    // K proj (pre-RoPE, fp32)
__device__ __half g_qh[S_LEN * NH * HD];    // Q RoPE'd, scaled, fp16
__device__ __half g_kh[S_LEN * NKV * HD];   // K RoPE'd, fp16
__device__ __half g_vh[NKV * HD * S_LEN];   // V transposed [dim][seq], fp16
__device__ __half g_oh[S_LEN * NH * HD];    // attention out, fp16
// pre-converted fp16 GEMM operands
__device__ __half g_xh[S_LEN * DIM];
__device__ __half g_wqh[NH * HD * DIM];
__device__ __half g_wkh[NKV * HD * DIM];
__device__ __half g_wvh[NKV * HD * DIM];
__device__ __half g_woh[DIM * NH * HD];

__device__ __forceinline__ void mma_f16(float* c, const uint32_t* a, const uint32_t* b) {
    asm volatile(
        "mma.sync.aligned.m16n8k16.row.col.f32.f16.f16.f32 "
        "{%0,%1,%2,%3}, {%4,%5,%6,%7}, {%8,%9}, {%0,%1,%2,%3};"
        : "+f"(c[0]), "+f"(c[1]), "+f"(c[2]), "+f"(c[3])
        : "r"(a[0]), "r"(a[1]), "r"(a[2]), "r"(a[3]), "r"(b[0]), "r"(b[1]));
}

__device__ __forceinline__ uint32_t pack_h2(float x, float y) {
    __half2 t = __floats2half2_rn(x, y);
    return *reinterpret_cast<uint32_t*>(&t);
}

__device__ __forceinline__ void cp16(void* smem_ptr, const void* gptr) {
    unsigned sa = (unsigned)__cvta_generic_to_shared(smem_ptr);
    asm volatile("cp.async.cg.shared.global [%0], [%1], 16;" :: "r"(sa), "l"(gptr));
}
#define CP_COMMIT() asm volatile("cp.async.commit_group;" ::: "memory")
#define CP_WAIT0()  asm volatile("cp.async.wait_group 0;" ::: "memory")

// ============================================================================
// Pre-convert fp32 -> fp16: x, wq, wk, wv, wo (single launch).
// ============================================================================
#define F4_X   1048576
#define F4_WQ  1048576
#define F4_WK  262144
#define F4_WV  262144
#define F4_WO  1048576

__global__ void conv5_kernel(const float4* __restrict__ x,
                             const float4* __restrict__ wq,
                             const float4* __restrict__ wk,
                             const float4* __restrict__ wv,
                             const float4* __restrict__ wo)
{
    int i = blockIdx.x * blockDim.x + threadIdx.x;
    const float4* s;
    __half* d;
    int off;
    if (i < F4_X)                       { s = x;  d = g_xh;  off = i; }
    else if (i < F4_X + F4_WQ)          { s = wq; d = g_wqh; off = i - F4_X; }
    else if (i < F4_X + F4_WQ + F4_WK)  { s = wk; d = g_wkh; off = i - F4_X - F4_WQ; }
    else if (i < F4_X + F4_WQ + F4_WK + F4_WV)
                                        { s = wv; d = g_wvh; off = i - F4_X - F4_WQ - F4_WK; }
    else                                { s = wo; d = g_woh; off = i - F4_X - F4_WQ - F4_WK - F4_WV; }
    float4 v = s[off];
    uint2 o;
    o.x = pack_h2(v.x, v.y);
    o.y = pack_h2(v.z, v.w);
    *(uint2*)(d + (size_t)off * 4) = o;
}

// ============================================================================
// FP16 GEMM NT core: C[m,n] = sum_k A[m,k]*B[n,k] + bias[n]
// Block 128x128x32 (k-slab 32), 8 warps, warp tile 32x64, m16n8k16 mma.
// 4-stage cp.async pipeline. Row stride 40 halves (20 words, == 4 mod 8)
// -> all fragment LDS.32 bank-conflict-free.
// EPI 0: fp32 C + bias. EPI 1: fp16 transposed [dim][seq] (V mode).
// ============================================================================
#define SMSH 40                 // halves per row
#define SMSW 20                 // words per row
#define A_H (128 * SMSH)        // halves per matrix per stage
#define STG_H (2 * A_H)         // halves per stage (A+B) = 10240 -> 20 KB

template <int EPI>
__device__ __forceinline__ void gemm_core_f16(
    const __half* __restrict__ A, const __half* __restrict__ B,
    const float* __restrict__ bias, float* __restrict__ C, __half* __restrict__ Ct,
    int N, int m0, int n0, __half* sm)
{
    const int tid = threadIdx.x;
    const int wid = tid >> 5;
    const int wm = wid & 3;
    const int wn = wid >> 2;
    const int l = tid & 31;
    const int l4 = l >> 2;
    const int lk = l & 3;
    const int lk2 = lk * 2;

    const int grow = tid >> 1;        // 0..127
    const int gc = (tid & 1) * 16;    // half offset within 32-half row chunk

    const __half* Ab = A + (size_t)(m0 + grow) * GK + gc;
    const __half* Bb = B + (size_t)(n0 + grow) * GK + gc;

    float acc[2][8][4];
    #pragma unroll
    for (int i = 0; i < 2; i++)
        #pragma unroll
        for (int j = 0; j < 8; j++)
            #pragma unroll
            for (int q = 0; q < 4; q++) acc[i][j][q] = 0.f;

    auto issue = [&](int slab, int slot) {
        __half* dst = sm + slot * STG_H + grow * SMSH + gc;
        const __half* as = Ab + slab * 32;
        cp16(dst, as);
        cp16(dst + 8, as + 8);
        __half* bdst = dst + A_H;
        const __half* bs = Bb + slab * 32;
        cp16(bdst, bs);
        cp16(bdst + 8, bs + 8);
        CP_COMMIT();
    };

    issue(0, 0);
    issue(1, 1);
    issue(2, 2);

    for (int s = 0; s < NSLAB; s++) {
        if (s <= NSLAB - 3)      asm volatile("cp.async.wait_group 2;" ::: "memory");
        else if (s == NSLAB - 2) asm volatile("cp.async.wait_group 1;" ::: "memory");
        else                     asm volatile("cp.async.wait_group 0;" ::: "memory");
        __syncthreads();

        const uint32_t* Aw = (const uint32_t*)(sm + (s & 3) * STG_H);
        const uint32_t* Bw = Aw + A_H / 2;
        #pragma unroll
        for (int ks = 0; ks < 2; ks++) {
            uint32_t a[2][4], b[8][2];
            #pragma unroll
            for (int tm = 0; tm < 2; tm++) {
                const uint32_t* base = Aw + (wm * 32 + tm * 16 + l4) * SMSW + ks * 8 + lk;
                a[tm][0] = base[0];
                a[tm][1] = base[8 * SMSW];
                a[tm][2] = base[4];
                a[tm][3] = base[8 * SMSW + 4];
            }
            #pragma unroll
            for (int tn = 0; tn < 8; tn++) {
                const uint32_t* bb = Bw + (wn * 64 + tn * 8 + l4) * SMSW + ks * 8 + lk;
                b[tn][0] = bb[0];
                b[tn][1] = bb[4];
            }
            #pragma unroll
            for (int tm = 0; tm < 2; tm++)
                #pragma unroll
                for (int tn = 0; tn < 8; tn++)
                    mma_f16(acc[tm][tn], a[tm], b[tn]);
        }

        if (s + 3 < NSLAB) issue(s + 3, (s + 3) & 3);
    }

    #pragma unroll
    for (int tm = 0; tm < 2; tm++) {
        const int row0 = m0 + wm * 32 + tm * 16 + l4;
        #pragma unroll
        for (int tn = 0; tn < 8; tn++) {
            const int col = n0 + wn * 64 + tn * 8 + lk2;
            const float b0 = bias[col];
            const float b1 = bias[col + 1];
            if (EPI == 0) {
                float2 v0 = make_float2(acc[tm][tn][0] + b0, acc[tm][tn][1] + b1);
                float2 v1 = make_float2(acc[tm][tn][2] + b0, acc[tm][tn][3] + b1);
                *(float2*)(C + (size_t)row0 * N + col) = v0;
                *(float2*)(C + (size_t)(row0 + 8) * N + col) = v1;
            } else {
                Ct[(size_t)col * S_LEN + row0]           = __float2half_rn(acc[tm][tn][0] + b0);
                Ct[(size_t)(col + 1) * S_LEN + row0]     = __float2half_rn(acc[tm][tn][1] + b1);
                Ct[(size_t)col * S_LEN + row0 + 8]       = __float2half_rn(acc[tm][tn][2] + b0);
                Ct[(size_t)(col + 1) * S_LEN + row0 + 8] = __float2half_rn(acc[tm][tn][3] + b1);
            }
        }
    }
}

__global__ void __launch_bounds__(256, 2) gemm_qkv(
    const float* __restrict__ wq_b, const float* __restrict__ wk_b,
    const float* __restrict__ wv_b)
{
    extern __shared__ __half sm[];
    int id = blockIdx.x;
    if (id < 256) {
        gemm_core_f16<0>(g_xh, g_wqh, wq_b, g_q, nullptr, NH * HD, (id >> 4) * 128, (id & 15) * 128, sm);
    } else if (id < 320) {
        id -= 256;
        gemm_core_f16<0>(g_xh, g_wkh, wk_b, g_k, nullptr, NKV * HD, (id >> 2) * 128, (id & 3) * 128, sm);
    } else {
        id -= 320;
        gemm_core_f16<1>(g_xh, g_wvh, wv_b, nullptr, g_vh, NKV * HD, (id >> 2) * 128, (id & 3) * 128, sm);
    }
}

__global__ void __launch_bounds__(256, 2) gemm_o(
    const float* __restrict__ wo_b, float* __restrict__ out)
{
    extern __shared__ __half sm[];
    const int id = blockIdx.x;
    gemm_core_f16<0>(g_oh, g_woh, wo_b, out, nullptr, DIM, (id >> 4) * 128, (id & 15) * 128, sm);
}

// ============================================================================
// RoPE: fp32 g_q/g_k -> fp16 g_qh (pre-scaled) / g_kh.
// ============================================================================
__global__ void rope_kernel(const float* __restrict__ rc)
{
    const int idx = blockIdx.x * blockDim.x + threadIdx.x;
    const int totalq = S_LEN * NH * 32;
    const int totalk = S_LEN * NKV * 32;
    if (idx < totalq) {
        const int d = idx & 31;
        const int sh = idx >> 5;
        const int h = sh & (NH - 1);
        const int s = sh >> 5;
        const float c = rc[s * HD + d];
        const float sn = rc[s * HD + 32 + d];
        const size_t base = ((size_t)s * NH + h) * HD;
        const float x1 = g_q[base + d], x2 = g_q[base + d + 32];
        g_qh[base + d]      = __float2half_rn((x1 * c - x2 * sn) * QK_SCALE);
        g_qh[base + d + 32] = __float2half_rn((x1 * sn + x2 * c) * QK_SCALE);
    } else if (idx < totalq + totalk) {
        const int e = idx - totalq;
        const int d = e & 31;
        const int sh = e >> 5;
        const int h = sh & (NKV - 1);
        const int s = sh >> 3;
        const float c = rc[s * HD + d];
        const float sn = rc[s * HD + 32 + d];
        const size_t base = ((size_t)s * NKV + h) * HD;
        const float x1 = g_k[base + d], x2 = g_k[base + d + 32];
        g_kh[base + d]      = __float2half_rn(x1 * c - x2 * sn);
        g_kh[base + d + 32] = __float2half_rn(x1 * sn + x2 * c);
    }
}

// ============================================================================
// Flash attention, FP16 m16n8k16, P in registers (direct half2 pack from the
// S C-fragment). cp.async double-buffered K/V staging. Row stride 72 halves
// (36 words == 4 mod 8) -> conflict-free fragment LDS.32.
// ============================================================================
#define FSTRH 72
#define FSTRW 36
#define FTILE_H (64 * FSTRH)    // 4608 halves per tile buffer

__global__ void __launch_bounds__(128, 3) flash_tc(const float* __restrict__ sinks)
{
    extern __shared__ __half fsm[];
    // layout: [K0][V0][K1][V1]
    const int h = blockIdx.y;
    const int kvh = h >> 2;
    const int qt = (int)gridDim.x - 1 - (int)blockIdx.x;   // heaviest first
    const int q0 = qt * 64;
    const int tid = threadIdx.x;
    const int w = tid >> 5;
    const int l = tid & 31;
    const int l4 = l >> 2;
    const int lk = l & 3;
    const int lk2 = lk * 2;

    // ---- stage Q tile via cp.async into buffer 0 (reused for K later) ----
    #pragma unroll
    for (int it = 0; it < 4; it++) {
        const int e = tid + it * 128;
        const int row = e >> 3, ch = e & 7;
        cp16(fsm + row * FSTRH + ch * 8,
             g_qh + (size_t)(q0 + row) * (NH * HD) + h * HD + ch * 8);
    }
    CP_COMMIT();
    CP_WAIT0();
    __syncthreads();

    uint32_t qf[4][4];
    {
        const uint32_t* Qw = (const uint32_t*)fsm;
        #pragma unroll
        for (int kc = 0; kc < 4; kc++) {
            const uint32_t* base = Qw + (w * 16 + l4) * FSTRW + kc * 8 + lk;
            qf[kc][0] = base[0];
            qf[kc][1] = base[8 * FSTRW];
            qf[kc][2] = base[4];
            qf[kc][3] = base[8 * FSTRW + 4];
        }
    }
    __syncthreads();   // qf reads done before K tile overwrites buffer 0

    auto issueKV = [&](int jt, int slot) {
        __half* Kb = fsm + slot * 2 * FTILE_H;
        __half* Vb = Kb + FTILE_H;
        const int j0 = jt * 64;
        #pragma unroll
        for (int it = 0; it < 4; it++) {
            const int e = tid + it * 128;
            const int row = e >> 3, ch = e & 7;
            cp16(Kb + row * FSTRH + ch * 8,
                 g_kh + (size_t)(j0 + row) * (NKV * HD) + kvh * HD + ch * 8);
            cp16(Vb + row * FSTRH + ch * 8,
                 g_vh + (size_t)(kvh * HD + row) * S_LEN + j0 + ch * 8);
        }
        CP_COMMIT();
    };

    float o[8][4];
    #pragma unroll
    for (int i = 0; i < 8; i++)
        #pragma unroll
        for (int j = 0; j < 4; j++) o[i][j] = 0.f;
    float m0 = -1e30f, m1 = -1e30f, l0 = 0.f, l1 = 0.f;

    issueKV(0, 0);

    for (int jt = 0; jt <= qt; jt++) {
        CP_WAIT0();
        __syncthreads();
        if (jt < qt) issueKV(jt + 1, (jt + 1) & 1);

        const uint32_t* Kw = (const uint32_t*)(fsm + (jt & 1) * 2 * FTILE_H);
        const uint32_t* Vw = Kw + FTILE_H / 2;

        // ---- S = Q K^T : 4 k-chunks of 16 dims ----
        float c[8][4];
        #pragma unroll
        for (int i = 0; i < 8; i++)
            #pragma unroll
            for (int j = 0; j < 4; j++) c[i][j] = 0.f;
        #pragma unroll
        for (int kc = 0; kc < 4; kc++) {
            #pragma unroll
            for (int nt = 0; nt < 8; nt++) {
                uint32_t b[2];
                const uint32_t* bb = Kw + (nt * 8 + l4) * FSTRW + kc * 8 + lk;
                b[0] = bb[0];
                b[1] = bb[4];
                mma_f16(c[nt], qf[kc], b);
            }
        }

        // ---- causal mask (diagonal tile only) ----
        if (jt == qt) {
            const int row0 = w * 16 + l4, row1 = row0 + 8;
            #pragma unroll
            for (int nt = 0; nt < 8; nt++) {
                const int col = nt * 8 + lk2;
                if (col > row0)     c[nt][0] = -1e30f;
                if (col + 1 > row0) c[nt][1] = -1e30f;
                if (col > row1)     c[nt][2] = -1e30f;
                if (col + 1 > row1) c[nt][3] = -1e30f;
            }
        }

        // ---- online softmax ----
        float rmax0 = -1e30f, rmax1 = -1e30f;
        #pragma unroll
        for (int nt = 0; nt < 8; nt++) {
            rmax0 = fmaxf(rmax0, fmaxf(c[nt][0], c[nt][1]));
            rmax1 = fmaxf(rmax1, fmaxf(c[nt][2], c[nt][3]));
        }
        rmax0 = fmaxf(rmax0, __shfl_xor_sync(0xffffffffu, rmax0, 1));
        rmax0 = fmaxf(rmax0, __shfl_xor_sync(0xffffffffu, rmax0, 2));
        rmax1 = fmaxf(rmax1, __shfl_xor_sync(0xffffffffu, rmax1, 1));
        rmax1 = fmaxf(rmax1, __shfl_xor_sync(0xffffffffu, rmax1, 2));

        const float mn0 = fmaxf(m0, rmax0);
        const float mn1 = fmaxf(m1, rmax1);
        const float al0 = __expf(m0 - mn0);
        const float al1 = __expf(m1 - mn1);
        m0 = mn0; m1 = mn1;

        float rs0 = 0.f, rs1 = 0.f;
        #pragma unroll
        for (int nt = 0; nt < 8; nt++) {
            c[nt][0] = __expf(c[nt][0] - mn0); rs0 += c[nt][0];
            c[nt][1] = __expf(c[nt][1] - mn0); rs0 += c[nt][1];
            c[nt][2] = __expf(c[nt][2] - mn1); rs1 += c[nt][2];
            c[nt][3] = __expf(c[nt][3] - mn1); rs1 += c[nt][3];
        }
        rs0 += __shfl_xor_sync(0xffffffffu, rs0, 1);
        rs0 += __shfl_xor_sync(0xffffffffu, rs0, 2);
        rs1 += __shfl_xor_sync(0xffffffffu, rs1, 1);
        rs1 += __shfl_xor_sync(0xffffffffu, rs1, 2);
        l0 = l0 * al0 + rs0;
        l1 = l1 * al1 + rs1;

        #pragma unroll
        for (int nt = 0; nt < 8; nt++) {
            o[nt][0] *= al0; o[nt][1] *= al0;
            o[nt][2] *= al1; o[nt][3] *= al1;
        }

        // ---- O += P V : P A-fragment packed directly from c regs ----
        #pragma unroll
        for (int kc = 0; kc < 4; kc++) {
            uint32_t a[4];
            a[0] = pack_h2(c[2 * kc][0],     c[2 * kc][1]);      // row l4,   keys 16kc+2lk,+1
            a[1] = pack_h2(c[2 * kc][2],     c[2 * kc][3]);      // row l4+8
            a[2] = pack_h2(c[2 * kc + 1][0], c[2 * kc + 1][1]);  // row l4,   keys 16kc+8+2lk,+1
            a[3] = pack_h2(c[2 * kc + 1][2], c[2 * kc + 1][3]);  // row l4+8
            #pragma unroll
            for (int nt = 0; nt < 8; nt++) {
                uint32_t b[2];
                const uint32_t* bb = Vw + (nt * 8 + l4) * FSTRW + kc * 8 + lk;
                b[0] = bb[0];
                b[1] = bb[4];
                mma_f16(o[nt], a, b);
            }
        }
        __syncthreads();   // reads of this tile done before next overwrite
    }

    // ---- epilogue: lse, sink sigmoid, normalize, store fp16 ----
    const float sk = sinks[h];
    const float lse0 = m0 + __logf(l0);
    const float lse1 = m1 + __logf(l1);
    const float w0 = (1.f / (1.f + __expf(sk - lse0))) / l0;
    const float w1 = (1.f / (1.f + __expf(sk - lse1))) / l1;
    const int row0 = q0 + w * 16 + l4;
    #pragma unroll
    for (int nt = 0; nt < 8; nt++) {
        const int col = h * HD + nt * 8 + lk2;
        *(uint32_t*)(g_oh + (size_t)row0 * (NH * HD) + col) =
            pack_h2(o[nt][0] * w0, o[nt][1] * w0);
        *(uint32_t*)(g_oh + (size_t)(row0 + 8) * (NH * HD) + col) =
            pack_h2(o[nt][2] * w1, o[nt][3] * w1);
    }
}

// ============================================================================
// launch
// ============================================================================
extern "C" void kernel_launch(void* const* d_in, const int* in_sizes, int n_in,
                              void* d_out, int out_size)
{
    const float* x     = (const float*)d_in[0];
    const float* rc    = (const float*)d_in[1];
    const float* wq_w  = (const float*)d_in[2];
    const float* wq_b  = (const float*)d_in[3];
    const float* wk_w  = (const float*)d_in[4];
    const float* wk_b  = (const float*)d_in[5];
    const float* wv_w  = (const float*)d_in[6];
    const float* wv_b  = (const float*)d_in[7];
    const float* wo_w  = (const float*)d_in[8];
    const float* wo_b  = (const float*)d_in[9];
    const float* sinks = (const float*)d_in[10];
    float* out = (float*)d_out;

    const int gemm_smem  = 4 * STG_H * 2;       // 80 KB (4 stages)
    const int flash_smem = 4 * FTILE_H * 2;     // 36 KB (2 stages x K,V)
    cudaFuncSetAttribute(gemm_qkv, cudaFuncAttributeMaxDynamicSharedMemorySize, gemm_smem);
    cudaFuncSetAttribute(gemm_o,   cudaFuncAttributeMaxDynamicSharedMemorySize, gemm_smem);
    cudaFuncSetAttribute(flash_tc, cudaFuncAttributeMaxDynamicSharedMemorySize, flash_smem);

    // 1. pre-convert x + weights to fp16
    conv5_kernel<<<(F4_X + F4_WQ + F4_WK + F4_WV + F4_WO) / 256, 256>>>(
        (const float4*)x, (const float4*)wq_w, (const float4*)wk_w,
        (const float4*)wv_w, (const float4*)wo_w);

    // 2. fused Q+K+V projections (V written transposed fp16)
    gemm_qkv<<<384, 256, gemm_smem>>>(wq_b, wk_b, wv_b);

    // 3. RoPE -> fp16 operand buffers
    {
        const int total = S_LEN * NH * 32 + S_LEN * NKV * 32;
        rope_kernel<<<(total + 255) / 256, 256>>>(rc);
    }

    // 4. flash attention
    flash_tc<<<dim3(S_LEN / 64, NH), 128, flash_smem>>>(sinks);

    // 5. output projection
    gemm_o<<<256, 256, gemm_smem>>>(wo_b, out);
}

// round 11
// speedup vs baseline: 2.7296x; 1.0500x over previous
#include <cuda_runtime.h>
#include <cuda_fp16.h>
#include <math.h>
#include <stdint.h>

#define S_LEN 2048
#define DIM 2048
#define NH 32
#define NKV 8
#define HD 64
#define QK_SCALE 0.125f
#define GK 2048
#define NSLAB 64           // K=2048 / 32
#define L2E 1.4426950408889634f

// ---- scratch (device globals; no allocation allowed) ----
__device__ __half g_qh[S_LEN * NH * HD];    // Q RoPE'd, scaled, fp16
__device__ __half g_kh[S_LEN * NKV * HD];   // K RoPE'd, fp16
__device__ __half g_vh[NKV * HD * S_LEN];   // V transposed [dim][seq], fp16
__device__ __half g_oh[S_LEN * NH * HD];    // attention out, fp16
// pre-converted fp16 GEMM operands
__device__ __half g_xh[S_LEN * DIM];
__device__ __half g_wqh[NH * HD * DIM];
__device__ __half g_wkh[NKV * HD * DIM];
__device__ __half g_wvh[NKV * HD * DIM];
__device__ __half g_woh[DIM * NH * HD];

__device__ __forceinline__ void mma_f16(float* c, const uint32_t* a, const uint32_t* b) {
    asm volatile(
        "mma.sync.aligned.m16n8k16.row.col.f32.f16.f16.f32 "
        "{%0,%1,%2,%3}, {%4,%5,%6,%7}, {%8,%9}, {%0,%1,%2,%3};"
        : "+f"(c[0]), "+f"(c[1]), "+f"(c[2]), "+f"(c[3])
        : "r"(a[0]), "r"(a[1]), "r"(a[2]), "r"(a[3]), "r"(b[0]), "r"(b[1]));
}

__device__ __forceinline__ uint32_t pack_h2(float x, float y) {
    __half2 t = __floats2half2_rn(x, y);
    return *reinterpret_cast<uint32_t*>(&t);
}

__device__ __forceinline__ uint32_t h2ex2(uint32_t x) {
    uint32_t r;
    asm("ex2.approx.f16x2 %0, %1;" : "=r"(r) : "r"(x));
    return r;
}

__device__ __forceinline__ void cp16(void* smem_ptr, const void* gptr) {
    unsigned sa = (unsigned)__cvta_generic_to_shared(smem_ptr);
    asm volatile("cp.async.cg.shared.global [%0], [%1], 16;" :: "r"(sa), "l"(gptr));
}
#define CP_COMMIT() asm volatile("cp.async.commit_group;" ::: "memory")
#define CP_WAIT0()  asm volatile("cp.async.wait_group 0;" ::: "memory")

// ============================================================================
// Pre-convert fp32 -> fp16: x, wq, wk, wv, wo (single launch).
// ============================================================================
#define F4_X   1048576
#define F4_WQ  1048576
#define F4_WK  262144
#define F4_WV  262144
#define F4_WO  1048576

__global__ void conv5_kernel(const float4* __restrict__ x,
                             const float4* __restrict__ wq,
                             const float4* __restrict__ wk,
                             const float4* __restrict__ wv,
                             const float4* __restrict__ wo)
{
    int i = blockIdx.x * blockDim.x + threadIdx.x;
    const float4* s;
    __half* d;
    int off;
    if (i < F4_X)                       { s = x;  d = g_xh;  off = i; }
    else if (i < F4_X + F4_WQ)          { s = wq; d = g_wqh; off = i - F4_X; }
    else if (i < F4_X + F4_WQ + F4_WK)  { s = wk; d = g_wkh; off = i - F4_X - F4_WQ; }
    else if (i < F4_X + F4_WQ + F4_WK + F4_WV)
                                        { s = wv; d = g_wvh; off = i - F4_X - F4_WQ - F4_WK; }
    else                                { s = wo; d = g_woh; off = i - F4_X - F4_WQ - F4_WK - F4_WV; }
    float4 v = s[off];
    uint2 o;
    o.x = pack_h2(v.x, v.y);
    o.y = pack_h2(v.z, v.w);
    *(uint2*)(d + (size_t)off * 4) = o;
}

// ============================================================================
// FP16 GEMM NT core: C[m,n] = sum_k A[m,k]*B[n,k] + bias[n]
// Block 128x128x32, 8 warps, warp tile 32x64, m16n8k16, 4-stage cp.async.
// Row stride 40 halves (20 words) -> conflict-free fragment LDS.32.
// EPI 0: fp32 C + bias (O proj).
// EPI 1: fp16 transposed [dim][seq] (V proj).
// EPI 2: RoPE + QK_SCALE -> fp16 (Q proj).   EPI 3: RoPE -> fp16 (K proj).
// ============================================================================
#define SMSH 40
#define SMSW 20
#define A_H (128 * SMSH)
#define STG_H (2 * A_H)

template <int EPI>
__device__ __forceinline__ void gemm_core_f16(
    const __half* __restrict__ A, const __half* __restrict__ B,
    const float* __restrict__ bias, float* __restrict__ C, __half* __restrict__ Ch,
    const float* __restrict__ rc,
    int N, int m0, int n0, __half* sm)
{
    const int tid = threadIdx.x;
    const int wid = tid >> 5;
    const int wm = wid & 3;
    const int wn = wid >> 2;
    const int l = tid & 31;
    const int l4 = l >> 2;
    const int lk = l & 3;
    const int lk2 = lk * 2;

    const int grow = tid >> 1;
    const int gc = (tid & 1) * 16;

    const __half* Ab = A + (size_t)(m0 + grow) * GK + gc;
    const __half* Bb = B + (size_t)(n0 + grow) * GK + gc;

    float acc[2][8][4];
    #pragma unroll
    for (int i = 0; i < 2; i++)
        #pragma unroll
        for (int j = 0; j < 8; j++)
            #pragma unroll
            for (int q = 0; q < 4; q++) acc[i][j][q] = 0.f;

    auto issue = [&](int slab, int slot) {
        __half* dst = sm + slot * STG_H + grow * SMSH + gc;
        const __half* as = Ab + slab * 32;
        cp16(dst, as);
        cp16(dst + 8, as + 8);
        __half* bdst = dst + A_H;
        const __half* bs = Bb + slab * 32;
        cp16(bdst, bs);
        cp16(bdst + 8, bs + 8);
        CP_COMMIT();
    };

    issue(0, 0);
    issue(1, 1);
    issue(2, 2);

    for (int s = 0; s < NSLAB; s++) {
        if (s <= NSLAB - 3)      asm volatile("cp.async.wait_group 2;" ::: "memory");
        else if (s == NSLAB - 2) asm volatile("cp.async.wait_group 1;" ::: "memory");
        else                     asm volatile("cp.async.wait_group 0;" ::: "memory");
        __syncthreads();

        const uint32_t* Aw = (const uint32_t*)(sm + (s & 3) * STG_H);
        const uint32_t* Bw = Aw + A_H / 2;
        #pragma unroll
        for (int ks = 0; ks < 2; ks++) {
            uint32_t a[2][4], b[8][2];
            #pragma unroll
            for (int tm = 0; tm < 2; tm++) {
                const uint32_t* base = Aw + (wm * 32 + tm * 16 + l4) * SMSW + ks * 8 + lk;
                a[tm][0] = base[0];
                a[tm][1] = base[8 * SMSW];
                a[tm][2] = base[4];
                a[tm][3] = base[8 * SMSW + 4];
            }
            #pragma unroll
            for (int tn = 0; tn < 8; tn++) {
                const uint32_t* bb = Bw + (wn * 64 + tn * 8 + l4) * SMSW + ks * 8 + lk;
                b[tn][0] = bb[0];
                b[tn][1] = bb[4];
            }
            #pragma unroll
            for (int tm = 0; tm < 2; tm++)
                #pragma unroll
                for (int tn = 0; tn < 8; tn++)
                    mma_f16(acc[tm][tn], a[tm], b[tn]);
        }

        if (s + 3 < NSLAB) issue(s + 3, (s + 3) & 3);
    }

    if (EPI <= 1) {
        #pragma unroll
        for (int tm = 0; tm < 2; tm++) {
            const int row0 = m0 + wm * 32 + tm * 16 + l4;
            #pragma unroll
            for (int tn = 0; tn < 8; tn++) {
                const int col = n0 + wn * 64 + tn * 8 + lk2;
                const float b0 = bias[col];
                const float b1 = bias[col + 1];
                if (EPI == 0) {
                    float2 v0 = make_float2(acc[tm][tn][0] + b0, acc[tm][tn][1] + b1);
                    float2 v1 = make_float2(acc[tm][tn][2] + b0, acc[tm][tn][3] + b1);
                    *(float2*)(C + (size_t)row0 * N + col) = v0;
                    *(float2*)(C + (size_t)(row0 + 8) * N + col) = v1;
                } else {
                    Ch[(size_t)col * S_LEN + row0]           = __float2half_rn(acc[tm][tn][0] + b0);
                    Ch[(size_t)(col + 1) * S_LEN + row0]     = __float2half_rn(acc[tm][tn][1] + b1);
                    Ch[(size_t)col * S_LEN + row0 + 8]       = __float2half_rn(acc[tm][tn][2] + b0);
                    Ch[(size_t)(col + 1) * S_LEN + row0 + 8] = __float2half_rn(acc[tm][tn][3] + b1);
                }
            }
        }
    } else {
        // RoPE epilogue: pair (tn, tn+4) = dims (d, d+32) of one head.
        #pragma unroll
        for (int tm = 0; tm < 2; tm++) {
            const int r0 = m0 + wm * 32 + tm * 16 + l4;
            #pragma unroll
            for (int tn = 0; tn < 4; tn++) {
                const int col = n0 + wn * 64 + tn * 8 + lk2;
                const int d = tn * 8 + lk2;
                const float b1a = bias[col],      b1b = bias[col + 1];
                const float b2a = bias[col + 32], b2b = bias[col + 33];
                #pragma unroll
                for (int rr = 0; rr < 2; rr++) {
                    const int row = r0 + rr * 8;
                    const float2 cs = *(const float2*)(rc + row * HD + d);
                    const float2 sn = *(const float2*)(rc + row * HD + 32 + d);
                    const float x1a = acc[tm][tn][rr * 2 + 0] + b1a;
                    const float x1b = acc[tm][tn][rr * 2 + 1] + b1b;
                    const float x2a = acc[tm][tn + 4][rr * 2 + 0] + b2a;
                    const float x2b = acc[tm][tn + 4][rr * 2 + 1] + b2b;
                    float o1a = x1a * cs.x - x2a * sn.x;
                    float o1b = x1b * cs.y - x2b * sn.y;
                    float o2a = x1a * sn.x + x2a * cs.x;
                    float o2b = x1b * sn.y + x2b * cs.y;
                    if (EPI == 2) {
                        o1a *= QK_SCALE; o1b *= QK_SCALE;
                        o2a *= QK_SCALE; o2b *= QK_SCALE;
                    }
                    *(uint32_t*)(Ch + (size_t)row * N + col)      = pack_h2(o1a, o1b);
                    *(uint32_t*)(Ch + (size_t)row * N + col + 32) = pack_h2(o2a, o2b);
                }
            }
        }
    }
}

__global__ void __launch_bounds__(256, 2) gemm_qkv(
    const float* __restrict__ wq_b, const float* __restrict__ wk_b,
    const float* __restrict__ wv_b, const float* __restrict__ rc)
{
    extern __shared__ __half sm[];
    int id = blockIdx.x;
    if (id < 256) {
        gemm_core_f16<2>(g_xh, g_wqh, wq_b, nullptr, g_qh, rc, NH * HD, (id >> 4) * 128, (id & 15) * 128, sm);
    } else if (id < 320) {
        id -= 256;
        gemm_core_f16<3>(g_xh, g_wkh, wk_b, nullptr, g_kh, rc, NKV * HD, (id >> 2) * 128, (id & 3) * 128, sm);
    } else {
        id -= 320;
        gemm_core_f16<1>(g_xh, g_wvh, wv_b, nullptr, g_vh, nullptr, NKV * HD, (id >> 2) * 128, (id & 3) * 128, sm);
    }
}

__global__ void __launch_bounds__(256, 2) gemm_o(
    const float* __restrict__ wo_b, float* __restrict__ out)
{
    extern __shared__ __half sm[];
    const int id = blockIdx.x;
    gemm_core_f16<0>(g_oh, g_woh, wo_b, out, nullptr, nullptr, DIM, (id >> 4) * 128, (id & 15) * 128, sm);
}

// ============================================================================
// Flash attention, FP16 m16n8k16, P in registers.
// P built as half2 A-fragments via ex2.approx.f16x2; row sums via one extra
// mma per kc against a ones vector (l needed only at the epilogue).
// cp.async double-buffered K/V staging. Stride 72 halves -> conflict-free.
// ============================================================================
#define FSTRH 72
#define FSTRW 36
#define FTILE_H (64 * FSTRH)

__global__ void __launch_bounds__(128, 3) flash_tc(const float* __restrict__ sinks)
{
    extern __shared__ __half fsm[];
    const int h = blockIdx.y;
    const int kvh = h >> 2;
    const int qt = (int)gridDim.x - 1 - (int)blockIdx.x;   // heaviest first
    const int q0 = qt * 64;
    const int tid = threadIdx.x;
    const int w = tid >> 5;
    const int l = tid & 31;
    const int l4 = l >> 2;
    const int lk = l & 3;
    const int lk2 = lk * 2;
    const uint32_t ONE2 = 0x3C003C00u;   // half2(1, 1)

    // ---- stage Q tile via cp.async into buffer 0 (reused for K later) ----
    #pragma unroll
    for (int it = 0; it < 4; it++) {
        const int e = tid + it * 128;
        const int row = e >> 3, ch = e & 7;
        cp16(fsm + row * FSTRH + ch * 8,
             g_qh + (size_t)(q0 + row) * (NH * HD) + h * HD + ch * 8);
    }
    CP_COMMIT();
    CP_WAIT0();
    __syncthreads();

    uint32_t qf[4][4];
    {
        const uint32_t* Qw = (const uint32_t*)fsm;
        #pragma unroll
        for (int kc = 0; kc < 4; kc++) {
            const uint32_t* base = Qw + (w * 16 + l4) * FSTRW + kc * 8 + lk;
            qf[kc][0] = base[0];
            qf[kc][1] = base[8 * FSTRW];
            qf[kc][2] = base[4];
            qf[kc][3] = base[8 * FSTRW + 4];
        }
    }
    __syncthreads();

    auto issueKV = [&](int jt, int slot) {
        __half* Kb = fsm + slot * 2 * FTILE_H;
        __half* Vb = Kb + FTILE_H;
        const int j0 = jt * 64;
        #pragma unroll
        for (int it = 0; it < 4; it++) {
            const int e = tid + it * 128;
            const int row = e >> 3, ch = e & 7;
            cp16(Kb + row * FSTRH + ch * 8,
                 g_kh + (size_t)(j0 + row) * (NKV * HD) + kvh * HD + ch * 8);
            cp16(Vb + row * FSTRH + ch * 8,
                 g_vh + (size_t)(kvh * HD + row) * S_LEN + j0 + ch * 8);
        }
        CP_COMMIT();
    };

    float o[8][4];
    #pragma unroll
    for (int i = 0; i < 8; i++)
        #pragma unroll
        for (int j = 0; j < 4; j++) o[i][j] = 0.f;
    float os[4] = {0.f, 0.f, 0.f, 0.f};
    float m0 = -1e30f, m1 = -1e30f;

    issueKV(0, 0);

    for (int jt = 0; jt <= qt; jt++) {
        CP_WAIT0();
        __syncthreads();
        if (jt < qt) issueKV(jt + 1, (jt + 1) & 1);

        const uint32_t* Kw = (const uint32_t*)(fsm + (jt & 1) * 2 * FTILE_H);
        const uint32_t* Vw = Kw + FTILE_H / 2;

        // ---- S = Q K^T ----
        float c[8][4];
        #pragma unroll
        for (int i = 0; i < 8; i++)
            #pragma unroll
            for (int j = 0; j < 4; j++) c[i][j] = 0.f;
        #pragma unroll
        for (int kc = 0; kc < 4; kc++) {
            #pragma unroll
            for (int nt = 0; nt < 8; nt++) {
                uint32_t b[2];
                const uint32_t* bb = Kw + (nt * 8 + l4) * FSTRW + kc * 8 + lk;
                b[0] = bb[0];
                b[1] = bb[4];
                mma_f16(c[nt], qf[kc], b);
            }
        }

        // ---- causal mask (diagonal tile only) ----
        if (jt == qt) {
            const int row0 = w * 16 + l4, row1 = row0 + 8;
            #pragma unroll
            for (int nt = 0; nt < 8; nt++) {
                const int col = nt * 8 + lk2;
                if (col > row0)     c[nt][0] = -1e30f;
                if (col + 1 > row0) c[nt][1] = -1e30f;
                if (col > row1)     c[nt][2] = -1e30f;
                if (col + 1 > row1) c[nt][3] = -1e30f;
            }
        }

        // ---- online max ----
        float rmax0 = -1e30f, rmax1 = -1e30f;
        #pragma unroll
        for (int nt = 0; nt < 8; nt++) {
            rmax0 = fmaxf(rmax0, fmaxf(c[nt][0], c[nt][1]));
            rmax1 = fmaxf(rmax1, fmaxf(c[nt][2], c[nt][3]));
        }
        rmax0 = fmaxf(rmax0, __shfl_xor_sync(0xffffffffu, rmax0, 1));
        rmax0 = fmaxf(rmax0, __shfl_xor_sync(0xffffffffu, rmax0, 2));
        rmax1 = fmaxf(rmax1, __shfl_xor_sync(0xffffffffu, rmax1, 1));
        rmax1 = fmaxf(rmax1, __shfl_xor_sync(0xffffffffu, rmax1, 2));

        const float mn0 = fmaxf(m0, rmax0);
        const float mn1 = fmaxf(m1, rmax1);
        const float al0 = __expf(m0 - mn0);
        const float al1 = __expf(m1 - mn1);
        m0 = mn0; m1 = mn1;
        const float mb0 = mn0 * L2E;
        const float mb1 = mn1 * L2E;

        #pragma unroll
        for (int nt = 0; nt < 8; nt++) {
            o[nt][0] *= al0; o[nt][1] *= al0;
            o[nt][2] *= al1; o[nt][3] *= al1;
        }
        os[0] *= al0; os[1] *= al0;
        os[2] *= al1; os[3] *= al1;

        // ---- P as half2 fragments; O += P V; row sums += P * 1 ----
        #pragma unroll
        for (int kc = 0; kc < 4; kc++) {
            uint32_t a[4];
            a[0] = h2ex2(pack_h2(fmaf(c[2 * kc][0], L2E, -mb0),
                                 fmaf(c[2 * kc][1], L2E, -mb0)));
            a[1] = h2ex2(pack_h2(fmaf(c[2 * kc][2], L2E, -mb1),
                                 fmaf(c[2 * kc][3], L2E, -mb1)));
            a[2] = h2ex2(pack_h2(fmaf(c[2 * kc + 1][0], L2E, -mb0),
                                 fmaf(c[2 * kc + 1][1], L2E, -mb0)));
            a[3] = h2ex2(pack_h2(fmaf(c[2 * kc + 1][2], L2E, -mb1),
                                 fmaf(c[2 * kc + 1][3], L2E, -mb1)));
            #pragma unroll
            for (int nt = 0; nt < 8; nt++) {
                uint32_t b[2];
                const uint32_t* bb = Vw + (nt * 8 + l4) * FSTRW + kc * 8 + lk;
                b[0] = bb[0];
                b[1] = bb[4];
                mma_f16(o[nt], a, b);
            }
            uint32_t bo[2] = {ONE2, ONE2};
            mma_f16(os, a, bo);
        }
        __syncthreads();
    }

    // ---- epilogue: lse, sink sigmoid, normalize, store fp16 ----
    const float l0 = os[0];
    const float l1 = os[2];
    const float sk = sinks[h];
    const float lse0 = m0 + __logf(l0);
    const float lse1 = m1 + __logf(l1);
    const float w0 = (1.f / (1.f + __expf(sk - lse0))) / l0;
    const float w1 = (1.f / (1.f + __expf(sk - lse1))) / l1;
    const int row0 = q0 + w * 16 + l4;
    #pragma unroll
    for (int nt = 0; nt < 8; nt++) {
        const int col = h * HD + nt * 8 + lk2;
        *(uint32_t*)(g_oh + (size_t)row0 * (NH * HD) + col) =
            pack_h2(o[nt][0] * w0, o[nt][1] * w0);
        *(uint32_t*)(g_oh + (size_t)(row0 + 8) * (NH * HD) + col) =
            pack_h2(o[nt][2] * w1, o[nt][3] * w1);
    }
}

// ============================================================================
// launch
// ============================================================================
extern "C" void kernel_launch(void* const* d_in, const int* in_sizes, int n_in,
                              void* d_out, int out_size)
{
    const float* x     = (const float*)d_in[0];
    const float* rc    = (const float*)d_in[1];
    const float* wq_w  = (const float*)d_in[2];
    const float* wq_b  = (const float*)d_in[3];
    const float* wk_w  = (const float*)d_in[4];
    const float* wk_b  = (const float*)d_in[5];
    const float* wv_w  = (const float*)d_in[6];
    const float* wv_b  = (const float*)d_in[7];
    const float* wo_w  = (const float*)d_in[8];
    const float* wo_b  = (const float*)d_in[9];
    const float* sinks = (const float*)d_in[10];
    float* out = (float*)d_out;

    const int gemm_smem  = 4 * STG_H * 2;       // 80 KB
    const int flash_smem = 4 * FTILE_H * 2;     // 36 KB
    cudaFuncSetAttribute(gemm_qkv, cudaFuncAttributeMaxDynamicSharedMemorySize, gemm_smem);
    cudaFuncSetAttribute(gemm_o,   cudaFuncAttributeMaxDynamicSharedMemorySize, gemm_smem);
    cudaFuncSetAttribute(flash_tc, cudaFuncAttributeMaxDynamicSharedMemorySize, flash_smem);

    // 1. pre-convert x + weights to fp16
    conv5_kernel<<<(F4_X + F4_WQ + F4_WK + F4_WV + F4_WO) / 256, 256>>>(
        (const float4*)x, (const float4*)wq_w, (const float4*)wk_w,
        (const float4*)wv_w, (const float4*)wo_w);

    // 2. fused Q+K+V projections (RoPE fused into Q/K epilogues)
    gemm_qkv<<<384, 256, gemm_smem>>>(wq_b, wk_b, wv_b, rc);

    // 3. flash attention
    flash_tc<<<dim3(S_LEN / 64, NH), 128, flash_smem>>>(sinks);

    // 4. output projection
    gemm_o<<<256, 256, gemm_smem>>>(wo_b, out);
}

// round 13
// speedup vs baseline: 3.0519x; 1.1181x over previous
#include <cuda_runtime.h>
#include <cuda_fp16.h>
#include <math.h>
#include <stdint.h>

#define S_LEN 2048
#define DIM 2048
#define NH 32
#define NKV 8
#define HD 64
#define QK_SCALE 0.125f
#define GK 2048
#define L2E 1.4426950408889634f

// ---- scratch (device globals; no allocation allowed) ----
__device__ __half g_qh[S_LEN * NH * HD];    // Q RoPE'd, scaled, fp16
__device__ __half g_kh[S_LEN * NKV * HD];   // K RoPE'd, fp16
__device__ __half g_vh[NKV * HD * S_LEN];   // V transposed [dim][seq], fp16
__device__ __half g_oh[S_LEN * NH * HD];    // attention out, fp16
__device__ __half g_xh[S_LEN * DIM];
__device__ __half g_wqh[NH * HD * DIM];
__device__ __half g_wkh[NKV * HD * DIM];
__device__ __half g_wvh[NKV * HD * DIM];
__device__ __half g_woh[DIM * NH * HD];

__device__ __forceinline__ void mma_f16(float* c, const uint32_t* a, const uint32_t* b) {
    asm volatile(
        "mma.sync.aligned.m16n8k16.row.col.f32.f16.f16.f32 "
        "{%0,%1,%2,%3}, {%4,%5,%6,%7}, {%8,%9}, {%0,%1,%2,%3};"
        : "+f"(c[0]), "+f"(c[1]), "+f"(c[2]), "+f"(c[3])
        : "r"(a[0]), "r"(a[1]), "r"(a[2]), "r"(a[3]), "r"(b[0]), "r"(b[1]));
}

__device__ __forceinline__ void ldsm4(uint32_t* r, uint32_t addr) {
    asm volatile("ldmatrix.sync.aligned.m8n8.x4.shared.b16 {%0,%1,%2,%3}, [%4];"
        : "=r"(r[0]), "=r"(r[1]), "=r"(r[2]), "=r"(r[3]) : "r"(addr));
}

__device__ __forceinline__ uint32_t pack_h2(float x, float y) {
    __half2 t = __floats2half2_rn(x, y);
    return *reinterpret_cast<uint32_t*>(&t);
}

__device__ __forceinline__ uint32_t h2ex2(uint32_t x) {
    uint32_t r;
    asm("ex2.approx.f16x2 %0, %1;" : "=r"(r) : "r"(x));
    return r;
}

__device__ __forceinline__ void cp16(void* smem_ptr, const void* gptr) {
    unsigned sa = (unsigned)__cvta_generic_to_shared(smem_ptr);
    asm volatile("cp.async.cg.shared.global [%0], [%1], 16;" :: "r"(sa), "l"(gptr));
}
#define CP_COMMIT() asm volatile("cp.async.commit_group;" ::: "memory")
#define CP_WAIT0()  asm volatile("cp.async.wait_group 0;" ::: "memory")

// ============================================================================
// Pre-convert fp32 -> fp16 (single launch).
// ============================================================================
#define F4_X   1048576
#define F4_WQ  1048576
#define F4_WK  262144
#define F4_WV  262144
#define F4_WO  1048576

__global__ void conv5_kernel(const float4* __restrict__ x,
                             const float4* __restrict__ wq,
                             const float4* __restrict__ wk,
                             const float4* __restrict__ wv,
                             const float4* __restrict__ wo)
{
    int i = blockIdx.x * blockDim.x + threadIdx.x;
    const float4* s;
    __half* d;
    int off;
    if (i < F4_X)                       { s = x;  d = g_xh;  off = i; }
    else if (i < F4_X + F4_WQ)          { s = wq; d = g_wqh; off = i - F4_X; }
    else if (i < F4_X + F4_WQ + F4_WK)  { s = wk; d = g_wkh; off = i - F4_X - F4_WQ; }
    else if (i < F4_X + F4_WQ + F4_WK + F4_WV)
                                        { s = wv; d = g_wvh; off = i - F4_X - F4_WQ - F4_WK; }
    else                                { s = wo; d = g_woh; off = i - F4_X - F4_WQ - F4_WK - F4_WV; }
    float4 v = s[off];
    uint2 o;
    o.x = pack_h2(v.x, v.y);
    o.y = pack_h2(v.z, v.w);
    *(uint2*)(d + (size_t)off * 4) = o;
}

// ============================================================================
// FP16 GEMM NT core: BK=64, 2-stage cp.async (double barrier), ldmatrix frags.
// Block 128x128x64, 8 warps, warp tile 32x64. Row stride 72 halves
// (36 words == 4 mod 8) -> conflict-free LDSM phases.
// EPI 0: fp32 C + bias. EPI 1: fp16 transposed (V). EPI 2/3: RoPE Q/K.
// ============================================================================
#define NSLAB 32                // K=2048 / 64
#define SMSH 72                 // halves per row
#define A_H (128 * SMSH)        // 9216 halves per matrix per stage
#define STG_H (2 * A_H)         // 18432 halves = 36864 B per stage

template <int EPI>
__device__ __forceinline__ void gemm_core_f16(
    const __half* __restrict__ A, const __half* __restrict__ B,
    const float* __restrict__ bias, float* __restrict__ C, __half* __restrict__ Ch,
    const float* __restrict__ rc,
    int N, int m0, int n0, __half* sm)
{
    const int tid = threadIdx.x;
    const int wid = tid >> 5;
    const int wm = wid & 3;
    const int wn = wid >> 2;
    const int l = tid & 31;
    const int l4 = l >> 2;
    const int lk2 = (l & 3) * 2;
    const int lrow = l & 15;            // ldmatrix lane row
    const int lcolh = (l >> 4) * 8;     // ldmatrix lane col (halves)

    const uint32_t smb = (uint32_t)__cvta_generic_to_shared(sm);

    // cp.async fill: row = e>>3 (0..127), ch = e&7 (8 x 16B chunks per 64-half row)
    const int frow = tid >> 3;          // wait: 256 threads/8 = 32 rows per pass
    const int fch = tid & 7;

    const __half* Ab = A + (size_t)(m0 + frow) * GK + fch * 8;
    const __half* Bb = B + (size_t)(n0 + frow) * GK + fch * 8;

    float acc[2][8][4];
    #pragma unroll
    for (int i = 0; i < 2; i++)
        #pragma unroll
        for (int j = 0; j < 8; j++)
            #pragma unroll
            for (int q = 0; q < 4; q++) acc[i][j][q] = 0.f;

    auto issue = [&](int slab, int slot) {
        __half* dst = sm + slot * STG_H;
        const int koff = slab * 64;
        #pragma unroll
        for (int i = 0; i < 4; i++) {
            const int row = frow + i * 32;
            cp16(dst + row * SMSH + fch * 8, Ab + (size_t)(i * 32) * GK + koff);
            cp16(dst + A_H + row * SMSH + fch * 8, Bb + (size_t)(i * 32) * GK + koff);
        }
        CP_COMMIT();
    };

    issue(0, 0);
    issue(1, 1);

    for (int s = 0; s < NSLAB; s++) {
        if (s < NSLAB - 1) asm volatile("cp.async.wait_group 1;" ::: "memory");
        else               asm volatile("cp.async.wait_group 0;" ::: "memory");
        __syncthreads();

        const uint32_t sb = smb + (s & 1) * (STG_H * 2);
        const uint32_t abase = sb + 2 * ((wm * 32 + lrow) * SMSH + lcolh);
        const uint32_t bbase = sb + 2 * (A_H + (wn * 64 + lrow) * SMSH + lcolh);

        #pragma unroll
        for (int ks = 0; ks < 4; ks++) {
            uint32_t a[2][4], bt[4][4];
            #pragma unroll
            for (int tm = 0; tm < 2; tm++)
                ldsm4(a[tm], abase + 2 * (tm * 16 * SMSH + ks * 16));
            #pragma unroll
            for (int nt2 = 0; nt2 < 4; nt2++)
                ldsm4(bt[nt2], bbase + 2 * (nt2 * 16 * SMSH + ks * 16));
            #pragma unroll
            for (int tm = 0; tm < 2; tm++)
                #pragma unroll
                for (int nt = 0; nt < 8; nt++) {
                    uint32_t b2[2] = { bt[nt >> 1][nt & 1], bt[nt >> 1][(nt & 1) + 2] };
                    mma_f16(acc[tm][nt], a[tm], b2);
                }
        }

        __syncthreads();
        if (s + 2 < NSLAB) issue(s + 2, s & 1);
    }

    if (EPI <= 1) {
        #pragma unroll
        for (int tm = 0; tm < 2; tm++) {
            const int row0 = m0 + wm * 32 + tm * 16 + l4;
            #pragma unroll
            for (int tn = 0; tn < 8; tn++) {
                const int col = n0 + wn * 64 + tn * 8 + lk2;
                const float b0 = bias[col];
                const float b1 = bias[col + 1];
                if (EPI == 0) {
                    float2 v0 = make_float2(acc[tm][tn][0] + b0, acc[tm][tn][1] + b1);
                    float2 v1 = make_float2(acc[tm][tn][2] + b0, acc[tm][tn][3] + b1);
                    *(float2*)(C + (size_t)row0 * N + col) = v0;
                    *(float2*)(C + (size_t)(row0 + 8) * N + col) = v1;
                } else {
                    Ch[(size_t)col * S_LEN + row0]           = __float2half_rn(acc[tm][tn][0] + b0);
                    Ch[(size_t)(col + 1) * S_LEN + row0]     = __float2half_rn(acc[tm][tn][1] + b1);
                    Ch[(size_t)col * S_LEN + row0 + 8]       = __float2half_rn(acc[tm][tn][2] + b0);
                    Ch[(size_t)(col + 1) * S_LEN + row0 + 8] = __float2half_rn(acc[tm][tn][3] + b1);
                }
            }
        }
    } else {
        // RoPE epilogue: pair (tn, tn+4) = dims (d, d+32) of one head.
        #pragma unroll
        for (int tm = 0; tm < 2; tm++) {
            const int r0 = m0 + wm * 32 + tm * 16 + l4;
            #pragma unroll
            for (int tn = 0; tn < 4; tn++) {
                const int col = n0 + wn * 64 + tn * 8 + lk2;
                const int d = tn * 8 + lk2;
                const float b1a = bias[col],      b1b = bias[col + 1];
                const float b2a = bias[col + 32], b2b = bias[col + 33];
                #pragma unroll
                for (int rr = 0; rr < 2; rr++) {
                    const int row = r0 + rr * 8;
                    const float2 cs = *(const float2*)(rc + row * HD + d);
                    const float2 sn = *(const float2*)(rc + row * HD + 32 + d);
                    const float x1a = acc[tm][tn][rr * 2 + 0] + b1a;
                    const float x1b = acc[tm][tn][rr * 2 + 1] + b1b;
                    const float x2a = acc[tm][tn + 4][rr * 2 + 0] + b2a;
                    const float x2b = acc[tm][tn + 4][rr * 2 + 1] + b2b;
                    float o1a = x1a * cs.x - x2a * sn.x;
                    float o1b = x1b * cs.y - x2b * sn.y;
                    float o2a = x1a * sn.x + x2a * cs.x;
                    float o2b = x1b * sn.y + x2b * cs.y;
                    if (EPI == 2) {
                        o1a *= QK_SCALE; o1b *= QK_SCALE;
                        o2a *= QK_SCALE; o2b *= QK_SCALE;
                    }
                    *(uint32_t*)(Ch + (size_t)row * N + col)      = pack_h2(o1a, o1b);
                    *(uint32_t*)(Ch + (size_t)row * N + col + 32) = pack_h2(o2a, o2b);
                }
            }
        }
    }
}

__global__ void __launch_bounds__(256, 2) gemm_qkv(
    const float* __restrict__ wq_b, const float* __restrict__ wk_b,
    const float* __restrict__ wv_b, const float* __restrict__ rc)
{
    extern __shared__ __half sm[];
    int id = blockIdx.x;
    if (id < 256) {
        gemm_core_f16<2>(g_xh, g_wqh, wq_b, nullptr, g_qh, rc, NH * HD, (id >> 4) * 128, (id & 15) * 128, sm);
    } else if (id < 320) {
        id -= 256;
        gemm_core_f16<3>(g_xh, g_wkh, wk_b, nullptr, g_kh, rc, NKV * HD, (id >> 2) * 128, (id & 3) * 128, sm);
    } else {
        id -= 320;
        gemm_core_f16<1>(g_xh, g_wvh, wv_b, nullptr, g_vh, nullptr, NKV * HD, (id >> 2) * 128, (id & 3) * 128, sm);
    }
}

__global__ void __launch_bounds__(256, 2) gemm_o(
    const float* __restrict__ wo_b, float* __restrict__ out)
{
    extern __shared__ __half sm[];
    const int id = blockIdx.x;
    gemm_core_f16<0>(g_oh, g_woh, wo_b, out, nullptr, nullptr, DIM, (id >> 4) * 128, (id & 15) * 128, sm);
}

// ============================================================================
// Flash attention, FP16 m16n8k16, P in registers, ldmatrix K/V/Q fragments,
// tensor-core row sums, cp.async double-buffered staging. Stride 72 halves.
// ============================================================================
#define FSTRH 72
#define FTILE_H (64 * FSTRH)

__global__ void __launch_bounds__(128, 3) flash_tc(const float* __restrict__ sinks)
{
    extern __shared__ __half fsm[];
    const int h = blockIdx.y;
    const int kvh = h >> 2;
    const int qt = (int)gridDim.x - 1 - (int)blockIdx.x;   // heaviest first
    const int q0 = qt * 64;
    const int tid = threadIdx.x;
    const int w = tid >> 5;
    const int l = tid & 31;
    const int l4 = l >> 2;
    const int lk2 = (l & 3) * 2;
    const int lrow = l & 15;
    const int lcolh = (l >> 4) * 8;
    const uint32_t ONE2 = 0x3C003C00u;
    const uint32_t fmb = (uint32_t)__cvta_generic_to_shared(fsm);

    // cp.async fill coords: row = e>>3 (64 rows), ch = e&7
    const int frow = tid >> 3;   // 0..15 per pass of 128 threads
    const int fch = tid & 7;

    // ---- stage Q tile into buffer 0 ----
    #pragma unroll
    for (int i = 0; i < 4; i++) {
        const int row = frow + i * 16;
        cp16(fsm + row * FSTRH + fch * 8,
             g_qh + (size_t)(q0 + row) * (NH * HD) + h * HD + fch * 8);
    }
    CP_COMMIT();
    CP_WAIT0();
    __syncthreads();

    uint32_t qf[4][4];
    {
        const uint32_t qbase = fmb + 2 * ((w * 16 + lrow) * FSTRH + lcolh);
        #pragma unroll
        for (int kc = 0; kc < 4; kc++)
            ldsm4(qf[kc], qbase + 2 * (kc * 16));
    }
    __syncthreads();

    auto issueKV = [&](int jt, int slot) {
        __half* Kb = fsm + slot * 2 * FTILE_H;
        __half* Vb = Kb + FTILE_H;
        const int j0 = jt * 64;
        #pragma unroll
        for (int i = 0; i < 4; i++) {
            const int row = frow + i * 16;
            cp16(Kb + row * FSTRH + fch * 8,
                 g_kh + (size_t)(j0 + row) * (NKV * HD) + kvh * HD + fch * 8);
            cp16(Vb + row * FSTRH + fch * 8,
                 g_vh + (size_t)(kvh * HD + row) * S_LEN + j0 + fch * 8);
        }
        CP_COMMIT();
    };

    float o[8][4];
    #pragma unroll
    for (int i = 0; i < 8; i++)
        #pragma unroll
        for (int j = 0; j < 4; j++) o[i][j] = 0.f;
    float os[4] = {0.f, 0.f, 0.f, 0.f};
    float m0 = -1e30f, m1 = -1e30f;

    issueKV(0, 0);

    for (int jt = 0; jt <= qt; jt++) {
        CP_WAIT0();
        __syncthreads();
        if (jt < qt) issueKV(jt + 1, (jt + 1) & 1);

        const uint32_t kb = fmb + (jt & 1) * (2 * FTILE_H * 2);
        const uint32_t vb = kb + FTILE_H * 2;
        const uint32_t kbase = kb + 2 * (lrow * FSTRH + lcolh);
        const uint32_t vbase = vb + 2 * (lrow * FSTRH + lcolh);

        // ---- S = Q K^T ----
        float c[8][4];
        #pragma unroll
        for (int i = 0; i < 8; i++)
            #pragma unroll
            for (int j = 0; j < 4; j++) c[i][j] = 0.f;
        #pragma unroll
        for (int kc = 0; kc < 4; kc++) {
            uint32_t bt[4][4];
            #pragma unroll
            for (int nt2 = 0; nt2 < 4; nt2++)
                ldsm4(bt[nt2], kbase + 2 * (nt2 * 16 * FSTRH + kc * 16));
            #pragma unroll
            for (int nt = 0; nt < 8; nt++) {
                uint32_t b2[2] = { bt[nt >> 1][nt & 1], bt[nt >> 1][(nt & 1) + 2] };
                mma_f16(c[nt], qf[kc], b2);
            }
        }

        // ---- causal mask (diagonal tile only) ----
        if (jt == qt) {
            const int row0 = w * 16 + l4, row1 = row0 + 8;
            #pragma unroll
            for (int nt = 0; nt < 8; nt++) {
                const int col = nt * 8 + lk2;
                if (col > row0)     c[nt][0] = -1e30f;
                if (col + 1 > row0) c[nt][1] = -1e30f;
                if (col > row1)     c[nt][2] = -1e30f;
                if (col + 1 > row1) c[nt][3] = -1e30f;
            }
        }

        // ---- online max ----
        float rmax0 = -1e30f, rmax1 = -1e30f;
        #pragma unroll
        for (int nt = 0; nt < 8; nt++) {
            rmax0 = fmaxf(rmax0, fmaxf(c[nt][0], c[nt][1]));
            rmax1 = fmaxf(rmax1, fmaxf(c[nt][2], c[nt][3]));
        }
        rmax0 = fmaxf(rmax0, __shfl_xor_sync(0xffffffffu, rmax0, 1));
        rmax0 = fmaxf(rmax0, __shfl_xor_sync(0xffffffffu, rmax0, 2));
        rmax1 = fmaxf(rmax1, __shfl_xor_sync(0xffffffffu, rmax1, 1));
        rmax1 = fmaxf(rmax1, __shfl_xor_sync(0xffffffffu, rmax1, 2));

        const float mn0 = fmaxf(m0, rmax0);
        const float mn1 = fmaxf(m1, rmax1);
        const float al0 = __expf(m0 - mn0);
        const float al1 = __expf(m1 - mn1);
        m0 = mn0; m1 = mn1;
        const float mb0 = mn0 * L2E;
        const float mb1 = mn1 * L2E;

        #pragma unroll
        for (int nt = 0; nt < 8; nt++) {
            o[nt][0] *= al0; o[nt][1] *= al0;
            o[nt][2] *= al1; o[nt][3] *= al1;
        }
        os[0] *= al0; os[1] *= al0;
        os[2] *= al1; os[3] *= al1;

        // ---- P as half2 fragments; O += P V; row sums += P * 1 ----
        #pragma unroll
        for (int kc = 0; kc < 4; kc++) {
            uint32_t a[4];
            a[0] = h2ex2(pack_h2(fmaf(c[2 * kc][0], L2E, -mb0),
                                 fmaf(c[2 * kc][1], L2E, -mb0)));
            a[1] = h2ex2(pack_h2(fmaf(c[2 * kc][2], L2E, -mb1),
                                 fmaf(c[2 * kc][3], L2E, -mb1)));
            a[2] = h2ex2(pack_h2(fmaf(c[2 * kc + 1][0], L2E, -mb0),
                                 fmaf(c[2 * kc + 1][1], L2E, -mb0)));
            a[3] = h2ex2(pack_h2(fmaf(c[2 * kc + 1][2], L2E, -mb1),
                                 fmaf(c[2 * kc + 1][3], L2E, -mb1)));
            uint32_t bt[4][4];
            #pragma unroll
            for (int nt2 = 0; nt2 < 4; nt2++)
                ldsm4(bt[nt2], vbase + 2 * (nt2 * 16 * FSTRH + kc * 16));
            #pragma unroll
            for (int nt = 0; nt < 8; nt++) {
                uint32_t b2[2] = { bt[nt >> 1][nt & 1], bt[nt >> 1][(nt & 1) + 2] };
                mma_f16(o[nt], a, b2);
            }
            uint32_t bo[2] = {ONE2, ONE2};
            mma_f16(os, a, bo);
        }
        __syncthreads();
    }

    // ---- epilogue: lse, sink sigmoid, normalize, store fp16 ----
    const float l0 = os[0];
    const float l1 = os[2];
    const float sk = sinks[h];
    const float lse0 = m0 + __logf(l0);
    const float lse1 = m1 + __logf(l1);
    const float w0 = (1.f / (1.f + __expf(sk - lse0))) / l0;
    const float w1 = (1.f / (1.f + __expf(sk - lse1))) / l1;
    const int row0 = q0 + w * 16 + l4;
    #pragma unroll
    for (int nt = 0; nt < 8; nt++) {
        const int col = h * HD + nt * 8 + lk2;
        *(uint32_t*)(g_oh + (size_t)row0 * (NH * HD) + col) =
            pack_h2(o[nt][0] * w0, o[nt][1] * w0);
        *(uint32_t*)(g_oh + (size_t)(row0 + 8) * (NH * HD) + col) =
            pack_h2(o[nt][2] * w1, o[nt][3] * w1);
    }
}

// ============================================================================
// launch
// ============================================================================
extern "C" void kernel_launch(void* const* d_in, const int* in_sizes, int n_in,
                              void* d_out, int out_size)
{
    const float* x     = (const float*)d_in[0];
    const float* rc    = (const float*)d_in[1];
    const float* wq_w  = (const float*)d_in[2];
    const float* wq_b  = (const float*)d_in[3];
    const float* wk_w  = (const float*)d_in[4];
    const float* wk_b  = (const float*)d_in[5];
    const float* wv_w  = (const float*)d_in[6];
    const float* wv_b  = (const float*)d_in[7];
    const float* wo_w  = (const float*)d_in[8];
    const float* wo_b  = (const float*)d_in[9];
    const float* sinks = (const float*)d_in[10];
    float* out = (float*)d_out;

    const int gemm_smem  = 2 * STG_H * 2;       // 73,728 B (2 stages)
    const int flash_smem = 4 * FTILE_H * 2;     // 36,864 B
    cudaFuncSetAttribute(gemm_qkv, cudaFuncAttributeMaxDynamicSharedMemorySize, gemm_smem);
    cudaFuncSetAttribute(gemm_o,   cudaFuncAttributeMaxDynamicSharedMemorySize, gemm_smem);
    cudaFuncSetAttribute(flash_tc, cudaFuncAttributeMaxDynamicSharedMemorySize, flash_smem);

    // 1. pre-convert x + weights to fp16
    conv5_kernel<<<(F4_X + F4_WQ + F4_WK + F4_WV + F4_WO) / 256, 256>>>(
        (const float4*)x, (const float4*)wq_w, (const float4*)wk_w,
        (const float4*)wv_w, (const float4*)wo_w);

    // 2. fused Q+K+V projections (RoPE fused into Q/K epilogues)
    gemm_qkv<<<384, 256, gemm_smem>>>(wq_b, wk_b, wv_b, rc);

    // 3. flash attention
    flash_tc<<<dim3(S_LEN / 64, NH), 128, flash_smem>>>(sinks);

    // 4. output projection
    gemm_o<<<256, 256, gemm_smem>>>(wo_b, out);
}

// round 14
// speedup vs baseline: 3.0564x; 1.0015x over previous
#include <cuda_runtime.h>
#include <cuda_fp16.h>
#include <math.h>
#include <stdint.h>

#define S_LEN 2048
#define DIM 2048
#define NH 32
#define NKV 8
#define HD 64
#define QK_SCALE 0.125f
#define GK 2048
#define L2E 1.4426950408889634f

// ---- scratch (device globals; no allocation allowed) ----
__device__ __half g_qh[S_LEN * NH * HD];    // Q RoPE'd, scaled, fp16
__device__ __half g_kh[S_LEN * NKV * HD];   // K RoPE'd, fp16
__device__ __half g_vh[NKV * HD * S_LEN];   // V transposed [dim][seq], fp16
__device__ __half g_oh[S_LEN * NH * HD];    // attention out, fp16
__device__ __half g_xh[S_LEN * DIM];
__device__ __half g_wqh[NH * HD * DIM];
__device__ __half g_wkh[NKV * HD * DIM];
__device__ __half g_wvh[NKV * HD * DIM];
__device__ __half g_woh[DIM * NH * HD];

__device__ __forceinline__ void mma_f16(float* c, const uint32_t* a, const uint32_t* b) {
    asm volatile(
        "mma.sync.aligned.m16n8k16.row.col.f32.f16.f16.f32 "
        "{%0,%1,%2,%3}, {%4,%5,%6,%7}, {%8,%9}, {%0,%1,%2,%3};"
        : "+f"(c[0]), "+f"(c[1]), "+f"(c[2]), "+f"(c[3])
        : "r"(a[0]), "r"(a[1]), "r"(a[2]), "r"(a[3]), "r"(b[0]), "r"(b[1]));
}

__device__ __forceinline__ void ldsm4(uint32_t* r, uint32_t addr) {
    asm volatile("ldmatrix.sync.aligned.m8n8.x4.shared.b16 {%0,%1,%2,%3}, [%4];"
        : "=r"(r[0]), "=r"(r[1]), "=r"(r[2]), "=r"(r[3]) : "r"(addr));
}

__device__ __forceinline__ uint32_t pack_h2(float x, float y) {
    __half2 t = __floats2half2_rn(x, y);
    return *reinterpret_cast<uint32_t*>(&t);
}

__device__ __forceinline__ uint32_t h2ex2(uint32_t x) {
    uint32_t r;
    asm("ex2.approx.f16x2 %0, %1;" : "=r"(r) : "r"(x));
    return r;
}

__device__ __forceinline__ void cp16(void* smem_ptr, const void* gptr) {
    unsigned sa = (unsigned)__cvta_generic_to_shared(smem_ptr);
    asm volatile("cp.async.cg.shared.global [%0], [%1], 16;" :: "r"(sa), "l"(gptr));
}
#define CP_COMMIT() asm volatile("cp.async.commit_group;" ::: "memory")
#define CP_WAIT0()  asm volatile("cp.async.wait_group 0;" ::: "memory")

// ============================================================================
// Pre-convert fp32 -> fp16 (single launch).
// ============================================================================
#define F4_X   1048576
#define F4_WQ  1048576
#define F4_WK  262144
#define F4_WV  262144
#define F4_WO  1048576

__global__ void conv5_kernel(const float4* __restrict__ x,
                             const float4* __restrict__ wq,
                             const float4* __restrict__ wk,
                             const float4* __restrict__ wv,
                             const float4* __restrict__ wo)
{
    int i = blockIdx.x * blockDim.x + threadIdx.x;
    const float4* s;
    __half* d;
    int off;
    if (i < F4_X)                       { s = x;  d = g_xh;  off = i; }
    else if (i < F4_X + F4_WQ)          { s = wq; d = g_wqh; off = i - F4_X; }
    else if (i < F4_X + F4_WQ + F4_WK)  { s = wk; d = g_wkh; off = i - F4_X - F4_WQ; }
    else if (i < F4_X + F4_WQ + F4_WK + F4_WV)
                                        { s = wv; d = g_wvh; off = i - F4_X - F4_WQ - F4_WK; }
    else                                { s = wo; d = g_woh; off = i - F4_X - F4_WQ - F4_WK - F4_WV; }
    float4 v = s[off];
    uint2 o;
    o.x = pack_h2(v.x, v.y);
    o.y = pack_h2(v.z, v.w);
    *(uint2*)(d + (size_t)off * 4) = o;
}

// ============================================================================
// FP16 GEMM NT core: BK=64, 2-stage cp.async (double barrier), ldmatrix frags.
// Block 128x128x64, 8 warps, warp tile 32x64. Row stride 72 halves
// (36 words == 4 mod 8) -> conflict-free LDSM phases.
// EPI 0: fp32 C + bias. EPI 1: fp16 transposed (V). EPI 2/3: RoPE Q/K.
// ============================================================================
#define NSLAB 32                // K=2048 / 64
#define SMSH 72                 // halves per row
#define A_H (128 * SMSH)        // 9216 halves per matrix per stage
#define STG_H (2 * A_H)         // 18432 halves = 36864 B per stage

template <int EPI>
__device__ __forceinline__ void gemm_core_f16(
    const __half* __restrict__ A, const __half* __restrict__ B,
    const float* __restrict__ bias, float* __restrict__ C, __half* __restrict__ Ch,
    const float* __restrict__ rc,
    int N, int m0, int n0, __half* sm)
{
    const int tid = threadIdx.x;
    const int wid = tid >> 5;
    const int wm = wid & 3;
    const int wn = wid >> 2;
    const int l = tid & 31;
    const int l4 = l >> 2;
    const int lk2 = (l & 3) * 2;
    const int lrow = l & 15;            // ldmatrix lane row
    const int lcolh = (l >> 4) * 8;     // ldmatrix lane col (halves)

    const uint32_t smb = (uint32_t)__cvta_generic_to_shared(sm);

    // cp.async fill: row = e>>3 (0..127), ch = e&7 (8 x 16B chunks per 64-half row)
    const int frow = tid >> 3;          // wait: 256 threads/8 = 32 rows per pass
    const int fch = tid & 7;

    const __half* Ab = A + (size_t)(m0 + frow) * GK + fch * 8;
    const __half* Bb = B + (size_t)(n0 + frow) * GK + fch * 8;

    float acc[2][8][4];
    #pragma unroll
    for (int i = 0; i < 2; i++)
        #pragma unroll
        for (int j = 0; j < 8; j++)
            #pragma unroll
            for (int q = 0; q < 4; q++) acc[i][j][q] = 0.f;

    auto issue = [&](int slab, int slot) {
        __half* dst = sm + slot * STG_H;
        const int koff = slab * 64;
        #pragma unroll
        for (int i = 0; i < 4; i++) {
            const int row = frow + i * 32;
            cp16(dst + row * SMSH + fch * 8, Ab + (size_t)(i * 32) * GK + koff);
            cp16(dst + A_H + row * SMSH + fch * 8, Bb + (size_t)(i * 32) * GK + koff);
        }
        CP_COMMIT();
    };

    issue(0, 0);
    issue(1, 1);

    for (int s = 0; s < NSLAB; s++) {
        if (s < NSLAB - 1) asm volatile("cp.async.wait_group 1;" ::: "memory");
        else               asm volatile("cp.async.wait_group 0;" ::: "memory");
        __syncthreads();

        const uint32_t sb = smb + (s & 1) * (STG_H * 2);
        const uint32_t abase = sb + 2 * ((wm * 32 + lrow) * SMSH + lcolh);
        const uint32_t bbase = sb + 2 * (A_H + (wn * 64 + lrow) * SMSH + lcolh);

        #pragma unroll
        for (int ks = 0; ks < 4; ks++) {
            uint32_t a[2][4], bt[4][4];
            #pragma unroll
            for (int tm = 0; tm < 2; tm++)
                ldsm4(a[tm], abase + 2 * (tm * 16 * SMSH + ks * 16));
            #pragma unroll
            for (int nt2 = 0; nt2 < 4; nt2++)
                ldsm4(bt[nt2], bbase + 2 * (nt2 * 16 * SMSH + ks * 16));
            #pragma unroll
            for (int tm = 0; tm < 2; tm++)
                #pragma unroll
                for (int nt = 0; nt < 8; nt++) {
                    uint32_t b2[2] = { bt[nt >> 1][nt & 1], bt[nt >> 1][(nt & 1) + 2] };
                    mma_f16(acc[tm][nt], a[tm], b2);
                }
        }

        __syncthreads();
        if (s + 2 < NSLAB) issue(s + 2, s & 1);
    }

    if (EPI <= 1) {
        #pragma unroll
        for (int tm = 0; tm < 2; tm++) {
            const int row0 = m0 + wm * 32 + tm * 16 + l4;
            #pragma unroll
            for (int tn = 0; tn < 8; tn++) {
                const int col = n0 + wn * 64 + tn * 8 + lk2;
                const float b0 = bias[col];
                const float b1 = bias[col + 1];
                if (EPI == 0) {
                    float2 v0 = make_float2(acc[tm][tn][0] + b0, acc[tm][tn][1] + b1);
                    float2 v1 = make_float2(acc[tm][tn][2] + b0, acc[tm][tn][3] + b1);
                    *(float2*)(C + (size_t)row0 * N + col) = v0;
                    *(float2*)(C + (size_t)(row0 + 8) * N + col) = v1;
                } else {
                    Ch[(size_t)col * S_LEN + row0]           = __float2half_rn(acc[tm][tn][0] + b0);
                    Ch[(size_t)(col + 1) * S_LEN + row0]     = __float2half_rn(acc[tm][tn][1] + b1);
                    Ch[(size_t)col * S_LEN + row0 + 8]       = __float2half_rn(acc[tm][tn][2] + b0);
                    Ch[(size_t)(col + 1) * S_LEN + row0 + 8] = __float2half_rn(acc[tm][tn][3] + b1);
                }
            }
        }
    } else {
        // RoPE epilogue: pair (tn, tn+4) = dims (d, d+32) of one head.
        #pragma unroll
        for (int tm = 0; tm < 2; tm++) {
            const int r0 = m0 + wm * 32 + tm * 16 + l4;
            #pragma unroll
            for (int tn = 0; tn < 4; tn++) {
                const int col = n0 + wn * 64 + tn * 8 + lk2;
                const int d = tn * 8 + lk2;
                const float b1a = bias[col],      b1b = bias[col + 1];
                const float b2a = bias[col + 32], b2b = bias[col + 33];
                #pragma unroll
                for (int rr = 0; rr < 2; rr++) {
                    const int row = r0 + rr * 8;
                    const float2 cs = *(const float2*)(rc + row * HD + d);
                    const float2 sn = *(const float2*)(rc + row * HD + 32 + d);
                    const float x1a = acc[tm][tn][rr * 2 + 0] + b1a;
                    const float x1b = acc[tm][tn][rr * 2 + 1] + b1b;
                    const float x2a = acc[tm][tn + 4][rr * 2 + 0] + b2a;
                    const float x2b = acc[tm][tn + 4][rr * 2 + 1] + b2b;
                    float o1a = x1a * cs.x - x2a * sn.x;
                    float o1b = x1b * cs.y - x2b * sn.y;
                    float o2a = x1a * sn.x + x2a * cs.x;
                    float o2b = x1b * sn.y + x2b * cs.y;
                    if (EPI == 2) {
                        o1a *= QK_SCALE; o1b *= QK_SCALE;
                        o2a *= QK_SCALE; o2b *= QK_SCALE;
                    }
                    *(uint32_t*)(Ch + (size_t)row * N + col)      = pack_h2(o1a, o1b);
                    *(uint32_t*)(Ch + (size_t)row * N + col + 32) = pack_h2(o2a, o2b);
                }
            }
        }
    }
}

__global__ void __launch_bounds__(256, 2) gemm_qkv(
    const float* __restrict__ wq_b, const float* __restrict__ wk_b,
    const float* __restrict__ wv_b, const float* __restrict__ rc)
{
    extern __shared__ __half sm[];
    int id = blockIdx.x;
    if (id < 256) {
        gemm_core_f16<2>(g_xh, g_wqh, wq_b, nullptr, g_qh, rc, NH * HD, (id >> 4) * 128, (id & 15) * 128, sm);
    } else if (id < 320) {
        id -= 256;
        gemm_core_f16<3>(g_xh, g_wkh, wk_b, nullptr, g_kh, rc, NKV * HD, (id >> 2) * 128, (id & 3) * 128, sm);
    } else {
        id -= 320;
        gemm_core_f16<1>(g_xh, g_wvh, wv_b, nullptr, g_vh, nullptr, NKV * HD, (id >> 2) * 128, (id & 3) * 128, sm);
    }
}

__global__ void __launch_bounds__(256, 2) gemm_o(
    const float* __restrict__ wo_b, float* __restrict__ out)
{
    extern __shared__ __half sm[];
    const int id = blockIdx.x;
    gemm_core_f16<0>(g_oh, g_woh, wo_b, out, nullptr, nullptr, DIM, (id >> 4) * 128, (id & 15) * 128, sm);
}

// ============================================================================
// Flash attention, FP16 m16n8k16, P in registers, ldmatrix K/V/Q fragments,
// tensor-core row sums, cp.async double-buffered staging. Stride 72 halves.
// ============================================================================
#define FSTRH 72
#define FTILE_H (64 * FSTRH)

__global__ void __launch_bounds__(128, 3) flash_tc(const float* __restrict__ sinks)
{
    extern __shared__ __half fsm[];
    const int h = blockIdx.y;
    const int kvh = h >> 2;
    const int qt = (int)gridDim.x - 1 - (int)blockIdx.x;   // heaviest first
    const int q0 = qt * 64;
    const int tid = threadIdx.x;
    const int w = tid >> 5;
    const int l = tid & 31;
    const int l4 = l >> 2;
    const int lk2 = (l & 3) * 2;
    const int lrow = l & 15;
    const int lcolh = (l >> 4) * 8;
    const uint32_t ONE2 = 0x3C003C00u;
    const uint32_t fmb = (uint32_t)__cvta_generic_to_shared(fsm);

    // cp.async fill coords: row = e>>3 (64 rows), ch = e&7
    const int frow = tid >> 3;   // 0..15 per pass of 128 threads
    const int fch = tid & 7;

    // ---- stage Q tile into buffer 0 ----
    #pragma unroll
    for (int i = 0; i < 4; i++) {
        const int row = frow + i * 16;
        cp16(fsm + row * FSTRH + fch * 8,
             g_qh + (size_t)(q0 + row) * (NH * HD) + h * HD + fch * 8);
    }
    CP_COMMIT();
    CP_WAIT0();
    __syncthreads();

    uint32_t qf[4][4];
    {
        const uint32_t qbase = fmb + 2 * ((w * 16 + lrow) * FSTRH + lcolh);
        #pragma unroll
        for (int kc = 0; kc < 4; kc++)
            ldsm4(qf[kc], qbase + 2 * (kc * 16));
    }
    __syncthreads();

    auto issueKV = [&](int jt, int slot) {
        __half* Kb = fsm + slot * 2 * FTILE_H;
        __half* Vb = Kb + FTILE_H;
        const int j0 = jt * 64;
        #pragma unroll
        for (int i = 0; i < 4; i++) {
            const int row = frow + i * 16;
            cp16(Kb + row * FSTRH + fch * 8,
                 g_kh + (size_t)(j0 + row) * (NKV * HD) + kvh * HD + fch * 8);
            cp16(Vb + row * FSTRH + fch * 8,
                 g_vh + (size_t)(kvh * HD + row) * S_LEN + j0 + fch * 8);
        }
        CP_COMMIT();
    };

    float o[8][4];
    #pragma unroll
    for (int i = 0; i < 8; i++)
        #pragma unroll
        for (int j = 0; j < 4; j++) o[i][j] = 0.f;
    float os[4] = {0.f, 0.f, 0.f, 0.f};
    float m0 = -1e30f, m1 = -1e30f;

    issueKV(0, 0);

    for (int jt = 0; jt <= qt; jt++) {
        CP_WAIT0();
        __syncthreads();
        if (jt < qt) issueKV(jt + 1, (jt + 1) & 1);

        const uint32_t kb = fmb + (jt & 1) * (2 * FTILE_H * 2);
        const uint32_t vb = kb + FTILE_H * 2;
        const uint32_t kbase = kb + 2 * (lrow * FSTRH + lcolh);
        const uint32_t vbase = vb + 2 * (lrow * FSTRH + lcolh);

        // ---- S = Q K^T ----
        float c[8][4];
        #pragma unroll
        for (int i = 0; i < 8; i++)
            #pragma unroll
            for (int j = 0; j < 4; j++) c[i][j] = 0.f;
        #pragma unroll
        for (int kc = 0; kc < 4; kc++) {
            uint32_t bt[4][4];
            #pragma unroll
            for (int nt2 = 0; nt2 < 4; nt2++)
                ldsm4(bt[nt2], kbase + 2 * (nt2 * 16 * FSTRH + kc * 16));
            #pragma unroll
            for (int nt = 0; nt < 8; nt++) {
                uint32_t b2[2] = { bt[nt >> 1][nt & 1], bt[nt >> 1][(nt & 1) + 2] };
                mma_f16(c[nt], qf[kc], b2);
            }
        }

        // ---- causal mask (diagonal tile only) ----
        if (jt == qt) {
            const int row0 = w * 16 + l4, row1 = row0 + 8;
            #pragma unroll
            for (int nt = 0; nt < 8; nt++) {
                const int col = nt * 8 + lk2;
                if (col > row0)     c[nt][0] = -1e30f;
                if (col + 1 > row0) c[nt][1] = -1e30f;
                if (col > row1)     c[nt][2] = -1e30f;
                if (col + 1 > row1) c[nt][3] = -1e30f;
            }
        }

        // ---- online max ----
        float rmax0 = -1e30f, rmax1 = -1e30f;
        #pragma unroll
        for (int nt = 0; nt < 8; nt++) {
            rmax0 = fmaxf(rmax0, fmaxf(c[nt][0], c[nt][1]));
            rmax1 = fmaxf(rmax1, fmaxf(c[nt][2], c[nt][3]));
        }
        rmax0 = fmaxf(rmax0, __shfl_xor_sync(0xffffffffu, rmax0, 1));
        rmax0 = fmaxf(rmax0, __shfl_xor_sync(0xffffffffu, rmax0, 2));
        rmax1 = fmaxf(rmax1, __shfl_xor_sync(0xffffffffu, rmax1, 1));
        rmax1 = fmaxf(rmax1, __shfl_xor_sync(0xffffffffu, rmax1, 2));

        const float mn0 = fmaxf(m0, rmax0);
        const float mn1 = fmaxf(m1, rmax1);
        const float al0 = __expf(m0 - mn0);
        const float al1 = __expf(m1 - mn1);
        m0 = mn0; m1 = mn1;
        const float mb0 = mn0 * L2E;
        const float mb1 = mn1 * L2E;

        #pragma unroll
        for (int nt = 0; nt < 8; nt++) {
            o[nt][0] *= al0; o[nt][1] *= al0;
            o[nt][2] *= al1; o[nt][3] *= al1;
        }
        os[0] *= al0; os[1] *= al0;
        os[2] *= al1; os[3] *= al1;

        // ---- P as half2 fragments; O += P V; row sums += P * 1 ----
        #pragma unroll
        for (int kc = 0; kc < 4; kc++) {
            uint32_t a[4];
            a[0] = h2ex2(pack_h2(fmaf(c[2 * kc][0], L2E, -mb0),
                                 fmaf(c[2 * kc][1], L2E, -mb0)));
            a[1] = h2ex2(pack_h2(fmaf(c[2 * kc][2], L2E, -mb1),
                                 fmaf(c[2 * kc][3], L2E, -mb1)));
            a[2] = h2ex2(pack_h2(fmaf(c[2 * kc + 1][0], L2E, -mb0),
                                 fmaf(c[2 * kc + 1][1], L2E, -mb0)));
            a[3] = h2ex2(pack_h2(fmaf(c[2 * kc + 1][2], L2E, -mb1),
                                 fmaf(c[2 * kc + 1][3], L2E, -mb1)));
            uint32_t bt[4][4];
            #pragma unroll
            for (int nt2 = 0; nt2 < 4; nt2++)
                ldsm4(bt[nt2], vbase + 2 * (nt2 * 16 * FSTRH + kc * 16));
            #pragma unroll
            for (int nt = 0; nt < 8; nt++) {
                uint32_t b2[2] = { bt[nt >> 1][nt & 1], bt[nt >> 1][(nt & 1) + 2] };
                mma_f16(o[nt], a, b2);
            }
            uint32_t bo[2] = {ONE2, ONE2};
            mma_f16(os, a, bo);
        }
        __syncthreads();
    }

    // ---- epilogue: lse, sink sigmoid, normalize, store fp16 ----
    const float l0 = os[0];
    const float l1 = os[2];
    const float sk = sinks[h];
    const float lse0 = m0 + __logf(l0);
    const float lse1 = m1 + __logf(l1);
    const float w0 = (1.f / (1.f + __expf(sk - lse0))) / l0;
    const float w1 = (1.f / (1.f + __expf(sk - lse1))) / l1;
    const int row0 = q0 + w * 16 + l4;
    #pragma unroll
    for (int nt = 0; nt < 8; nt++) {
        const int col = h * HD + nt * 8 + lk2;
        *(uint32_t*)(g_oh + (size_t)row0 * (NH * HD) + col) =
            pack_h2(o[nt][0] * w0, o[nt][1] * w0);
        *(uint32_t*)(g_oh + (size_t)(row0 + 8) * (NH * HD) + col) =
            pack_h2(o[nt][2] * w1, o[nt][3] * w1);
    }
}

// ============================================================================
// launch
// ============================================================================
extern "C" void kernel_launch(void* const* d_in, const int* in_sizes, int n_in,
                              void* d_out, int out_size)
{
    const float* x     = (const float*)d_in[0];
    const float* rc    = (const float*)d_in[1];
    const float* wq_w  = (const float*)d_in[2];
    const float* wq_b  = (const float*)d_in[3];
    const float* wk_w  = (const float*)d_in[4];
    const float* wk_b  = (const float*)d_in[5];
    const float* wv_w  = (const float*)d_in[6];
    const float* wv_b  = (const float*)d_in[7];
    const float* wo_w  = (const float*)d_in[8];
    const float* wo_b  = (const float*)d_in[9];
    const float* sinks = (const float*)d_in[10];
    float* out = (float*)d_out;

    const int gemm_smem  = 2 * STG_H * 2;       // 73,728 B (2 stages)
    const int flash_smem = 4 * FTILE_H * 2;     // 36,864 B
    cudaFuncSetAttribute(gemm_qkv, cudaFuncAttributeMaxDynamicSharedMemorySize, gemm_smem);
    cudaFuncSetAttribute(gemm_o,   cudaFuncAttributeMaxDynamicSharedMemorySize, gemm_smem);
    cudaFuncSetAttribute(flash_tc, cudaFuncAttributeMaxDynamicSharedMemorySize, flash_smem);

    // 1. pre-convert x + weights to fp16
    conv5_kernel<<<(F4_X + F4_WQ + F4_WK + F4_WV + F4_WO) / 256, 256>>>(
        (const float4*)x, (const float4*)wq_w, (const float4*)wk_w,
        (const float4*)wv_w, (const float4*)wo_w);

    // 2. fused Q+K+V projections (RoPE fused into Q/K epilogues)
    gemm_qkv<<<384, 256, gemm_smem>>>(wq_b, wk_b, wv_b, rc);

    // 3. flash attention
    flash_tc<<<dim3(S_LEN / 64, NH), 128, flash_smem>>>(sinks);

    // 4. output projection
    gemm_o<<<256, 256, gemm_smem>>>(wo_b, out);
}